// round 5
// baseline (speedup 1.0000x reference)
#include <cuda_runtime.h>
#include <cstdint>

#define HID   1024
#define BATCH 2
#define SKV   4096
#define SQ    512
#define NH    16
#define NHK   4
#define DH    64

// ---------------- scratch ----------------
__device__ float g_Q [BATCH * SQ  * NH  * DH];
__device__ float g_K [BATCH * SKV * NHK * DH];
__device__ float g_V [BATCH * SKV * NHK * DH];
__device__ float g_AO[BATCH * SQ  * NH  * DH];

// ---------------- helpers ----------------
__device__ __forceinline__ uint32_t f2tf(float f) {
    uint32_t u;
    asm("cvt.rna.tf32.f32 %0, %1;" : "=r"(u) : "f"(f));
    return u;
}
__device__ __forceinline__ void tfsplit(float f, uint32_t& h, uint32_t& l) {
    h = f2tf(f);
    l = f2tf(f - __uint_as_float(h));
}
__device__ __forceinline__ float4 f2tf4(float4 v) {
    float4 r;
    r.x = __uint_as_float(f2tf(v.x));
    r.y = __uint_as_float(f2tf(v.y));
    r.z = __uint_as_float(f2tf(v.z));
    r.w = __uint_as_float(f2tf(v.w));
    return r;
}
// D += A * B  (m16n8k8 tf32, A row-major, B col-major)
__device__ __forceinline__ void mma8(float* d, const uint32_t* a, const uint32_t* b) {
    asm volatile(
        "mma.sync.aligned.m16n8k8.row.col.f32.tf32.tf32.f32 "
        "{%0,%1,%2,%3},{%4,%5,%6,%7},{%8,%9},{%0,%1,%2,%3};"
        : "+f"(d[0]), "+f"(d[1]), "+f"(d[2]), "+f"(d[3])
        : "r"(a[0]), "r"(a[1]), "r"(a[2]), "r"(a[3]), "r"(b[0]), "r"(b[1]));
}

// ======================================================================
// GEMM: C[M,N] = A[M,K] @ W[N,K]^T, tf32 mma.sync.
// Single-copy smem staging; PASSES==3: raw f32 staged, hi/lo rna-split at
// fragment load. PASSES==1: rna-rounded tf32 staged at STS.
// Double-buffered + register prefetch: 1 syncthreads per K-chunk.
// BM=128, BN=64, BK=32. 256 threads = 8 warps (4 M x 2 N).
// ======================================================================
template <int PASSES, bool NORM>
__global__ void __launch_bounds__(256) gemm_tc(
    const float* __restrict__ A, const float* __restrict__ W,
    const float* __restrict__ nw, float* __restrict__ C,
    int M, int N, int Kdim)
{
    extern __shared__ float sm[];
    constexpr int AP = 36;
    constexpr int BUFG = (128 + 64) * AP;    // 6912 floats
    float* red = sm + 2 * BUFG;

    const int tid = threadIdx.x, lane = tid & 31, wid = tid >> 5;
    const int wm = wid >> 1, wn = wid & 1;
    const int g = lane >> 2, c = lane & 3;
    const int m0 = blockIdx.y * 128, n0 = blockIdx.x * 64;

    float acc[2][4][4];
#pragma unroll
    for (int mt = 0; mt < 2; mt++)
#pragma unroll
        for (int nt = 0; nt < 4; nt++)
#pragma unroll
            for (int i = 0; i < 4; i++) acc[mt][nt][i] = 0.f;

    const int arow = tid >> 1, acol = (tid & 1) * 16;
    const int wrow = tid >> 2, wcol = (tid & 3) * 8;
    const float* Ap = A + (size_t)(m0 + arow) * Kdim + acol;
    const float* Wp = W + (size_t)(n0 + wrow) * Kdim + wcol;

    float4 areg[4], wreg[2];
    auto LDGS = [&](int kt) {
#pragma unroll
        for (int i = 0; i < 4; i++) areg[i] = *(const float4*)(Ap + kt + i * 4);
#pragma unroll
        for (int i = 0; i < 2; i++) wreg[i] = *(const float4*)(Wp + kt + i * 4);
    };
    auto STSS = [&](int buf) {
        float* Ar = sm + buf * BUFG;
        float* Wr = Ar + 128 * AP;
#pragma unroll
        for (int i = 0; i < 4; i++) {
            float4 v = (PASSES == 1) ? f2tf4(areg[i]) : areg[i];
            *(float4*)(Ar + arow * AP + acol + i * 4) = v;
        }
#pragma unroll
        for (int i = 0; i < 2; i++) {
            float4 v = (PASSES == 1) ? f2tf4(wreg[i]) : wreg[i];
            *(float4*)(Wr + wrow * AP + wcol + i * 4) = v;
        }
    };

    LDGS(0); STSS(0);
    __syncthreads();

    for (int kt = 0; kt < Kdim; kt += 32) {
        const int cur = (kt >> 5) & 1;
        const bool more = (kt + 32 < Kdim);
        if (more) LDGS(kt + 32);

        const float* Ar = sm + cur * BUFG;
        const float* Wr = Ar + 128 * AP;

#pragma unroll
        for (int s = 0; s < 4; s++) {
            uint32_t ah[2][4], al[2][4], bh[4][2], bl[4][2];
#pragma unroll
            for (int mt = 0; mt < 2; mt++) {
                const int r = wm * 32 + mt * 16;
                float f0 = Ar[(r + g) * AP + s * 8 + c];
                float f1 = Ar[(r + g + 8) * AP + s * 8 + c];
                float f2 = Ar[(r + g) * AP + s * 8 + c + 4];
                float f3 = Ar[(r + g + 8) * AP + s * 8 + c + 4];
                if constexpr (PASSES == 3) {
                    tfsplit(f0, ah[mt][0], al[mt][0]);
                    tfsplit(f1, ah[mt][1], al[mt][1]);
                    tfsplit(f2, ah[mt][2], al[mt][2]);
                    tfsplit(f3, ah[mt][3], al[mt][3]);
                } else {
                    ah[mt][0] = __float_as_uint(f0); ah[mt][1] = __float_as_uint(f1);
                    ah[mt][2] = __float_as_uint(f2); ah[mt][3] = __float_as_uint(f3);
                }
            }
#pragma unroll
            for (int nt = 0; nt < 4; nt++) {
                const int n = wn * 32 + nt * 8 + g;
                float f0 = Wr[n * AP + s * 8 + c];
                float f1 = Wr[n * AP + s * 8 + c + 4];
                if constexpr (PASSES == 3) {
                    tfsplit(f0, bh[nt][0], bl[nt][0]);
                    tfsplit(f1, bh[nt][1], bl[nt][1]);
                } else {
                    bh[nt][0] = __float_as_uint(f0); bh[nt][1] = __float_as_uint(f1);
                }
            }
#pragma unroll
            for (int mt = 0; mt < 2; mt++)
#pragma unroll
                for (int nt = 0; nt < 4; nt++) {
                    mma8(acc[mt][nt], ah[mt], bh[nt]);
                    if constexpr (PASSES == 3) {
                        mma8(acc[mt][nt], al[mt], bh[nt]);
                        mma8(acc[mt][nt], ah[mt], bl[nt]);
                    }
                }
        }
        if (more) {
            STSS(1 - cur);
            __syncthreads();
        }
    }

    if (NORM) {
        __syncthreads();
        float ss0[2] = {0.f, 0.f}, ss1[2] = {0.f, 0.f};
#pragma unroll
        for (int mt = 0; mt < 2; mt++)
#pragma unroll
            for (int nt = 0; nt < 4; nt++) {
                ss0[mt] += acc[mt][nt][0] * acc[mt][nt][0] + acc[mt][nt][1] * acc[mt][nt][1];
                ss1[mt] += acc[mt][nt][2] * acc[mt][nt][2] + acc[mt][nt][3] * acc[mt][nt][3];
            }
#pragma unroll
        for (int mt = 0; mt < 2; mt++) {
            ss0[mt] += __shfl_xor_sync(0xffffffffu, ss0[mt], 1);
            ss0[mt] += __shfl_xor_sync(0xffffffffu, ss0[mt], 2);
            ss1[mt] += __shfl_xor_sync(0xffffffffu, ss1[mt], 1);
            ss1[mt] += __shfl_xor_sync(0xffffffffu, ss1[mt], 2);
            if (c == 0) {
                red[(wm * 32 + mt * 16 + g) * 2 + wn]     = ss0[mt];
                red[(wm * 32 + mt * 16 + g + 8) * 2 + wn] = ss1[mt];
            }
        }
        __syncthreads();
        float sc0[2], sc1[2];
#pragma unroll
        for (int mt = 0; mt < 2; mt++) {
            int r = (wm * 32 + mt * 16 + g) * 2;
            sc0[mt] = rsqrtf((red[r] + red[r + 1]) * (1.f / 64.f) + 1e-6f);
            r = (wm * 32 + mt * 16 + g + 8) * 2;
            sc1[mt] = rsqrtf((red[r] + red[r + 1]) * (1.f / 64.f) + 1e-6f);
        }
        float w0[4], w1[4];
#pragma unroll
        for (int nt = 0; nt < 4; nt++) {
            w0[nt] = nw[wn * 32 + nt * 8 + 2 * c];
            w1[nt] = nw[wn * 32 + nt * 8 + 2 * c + 1];
        }
#pragma unroll
        for (int mt = 0; mt < 2; mt++)
#pragma unroll
            for (int nt = 0; nt < 4; nt++) {
                acc[mt][nt][0] *= sc0[mt] * w0[nt];
                acc[mt][nt][1] *= sc0[mt] * w1[nt];
                acc[mt][nt][2] *= sc1[mt] * w0[nt];
                acc[mt][nt][3] *= sc1[mt] * w1[nt];
            }
    }

#pragma unroll
    for (int mt = 0; mt < 2; mt++)
#pragma unroll
        for (int nt = 0; nt < 4; nt++) {
            int r = m0 + wm * 32 + mt * 16 + g;
            int col = n0 + wn * 32 + nt * 8 + 2 * c;
            *(float2*)(C + (size_t)r * N + col) =
                make_float2(acc[mt][nt][0], acc[mt][nt][1]);
            *(float2*)(C + (size_t)(r + 8) * N + col) =
                make_float2(acc[mt][nt][2], acc[mt][nt][3]);
        }
}

// ======================================================================
// Attention, mma.sync tf32. CTA = 128 rows (4 heads x 32 q) of one (b,hk).
// 8 warps x 16 rows. KV tile 64, double-buffered smem:
//   K staged raw f32 (hi/lo rna-split at fragment load, 3xTF32 QK^T);
//   V staged rna-rounded tf32 (1xTF32 PV).
// P rounded to tf32 BEFORE both row-sum and store (numerator/denominator
// consistency). No-max softmax: |s| <= 64 so exp stays finite in fp32.
// ======================================================================
__global__ void __launch_bounds__(256, 1) attn_mma(
    const float* __restrict__ Qg, const float* __restrict__ Kg,
    const float* __restrict__ Vg, float* __restrict__ Og)
{
    extern __shared__ float sm[];
    constexpr int KP = 68, VP = 72, PP = 76;
    constexpr int BUF = 64 * KP + 64 * VP;   // 8960 floats / buffer
    float* Ps = sm + 2 * BUF;

    const int tid = threadIdx.x;
    const int lane = tid & 31, w = tid >> 5;
    const int g = lane >> 2, c = lane & 3;
    const int b = blockIdx.z, hk = blockIdx.y, q0 = blockIdx.x * 32;
    const int head = hk * 4 + (w >> 1);
    const int qi = (w & 1) * 16;

    // ---- Q fragments (hi/lo tf32), persistent in registers ----
    uint32_t qh[8][4], ql[8][4];
    {
        const float* r0 = Qg + (size_t)(b * SQ + q0 + qi + g) * HID + head * DH;
        const float* r1 = r0 + 8 * (size_t)HID;
#pragma unroll
        for (int s = 0; s < 8; s++) {
            tfsplit(r0[s * 8 + c],     qh[s][0], ql[s][0]);
            tfsplit(r1[s * 8 + c],     qh[s][1], ql[s][1]);
            tfsplit(r0[s * 8 + c + 4], qh[s][2], ql[s][2]);
            tfsplit(r1[s * 8 + c + 4], qh[s][3], ql[s][3]);
        }
    }

    const int krow = tid >> 2;
    const int kcol = (tid & 3) * 16;
    const float* kbase = Kg + (size_t)b * SKV * (NHK * DH) + hk * DH + kcol;
    const float* vbase = Vg + (size_t)b * SKV * (NHK * DH) + hk * DH + kcol;

    float4 kr[4], vr[4];
    auto LDG = [&](int t) {
        const float* kp = kbase + (size_t)(t * 64 + krow) * (NHK * DH);
        const float* vp = vbase + (size_t)(t * 64 + krow) * (NHK * DH);
#pragma unroll
        for (int i = 0; i < 4; i++) {
            kr[i] = *(const float4*)(kp + i * 4);
            vr[i] = *(const float4*)(vp + i * 4);
        }
    };
    auto STS = [&](int buf) {
        float* KR = sm + buf * BUF;
        float* VV = KR + 64 * KP;
#pragma unroll
        for (int i = 0; i < 4; i++) {
            *(float4*)(KR + krow * KP + kcol + i * 4) = kr[i];
            *(float4*)(VV + krow * VP + kcol + i * 4) = f2tf4(vr[i]);
        }
    };

    float oacc[8][4];
#pragma unroll
    for (int j = 0; j < 8; j++)
#pragma unroll
        for (int i = 0; i < 4; i++) oacc[j][i] = 0.f;
    float lsum0 = 0.f, lsum1 = 0.f;
    float* Pw = Ps + w * 16 * PP;

    LDG(0); STS(0);
    __syncthreads();

    for (int t = 0; t < SKV / 64; t++) {
        const int cur = t & 1;
        if (t < SKV / 64 - 1) LDG(t + 1);
        const float* KR = sm + cur * BUF;
        const float* VV = KR + 64 * KP;

        // --- S = Q @ K^T (3xTF32, split-on-load) ---
        float sacc[8][4];
#pragma unroll
        for (int j = 0; j < 8; j++)
#pragma unroll
            for (int i = 0; i < 4; i++) sacc[j][i] = 0.f;
#pragma unroll
        for (int s = 0; s < 8; s++) {
#pragma unroll
            for (int j = 0; j < 8; j++) {
                const int ba = (j * 8 + g) * KP + s * 8 + c;
                uint32_t bh[2], bl[2];
                tfsplit(KR[ba],     bh[0], bl[0]);
                tfsplit(KR[ba + 4], bh[1], bl[1]);
                mma8(sacc[j], qh[s], bh);
                mma8(sacc[j], ql[s], bh);
                mma8(sacc[j], qh[s], bl);
            }
        }

        // --- P = exp(S), tf32-rounded before sum AND store ---
        float rs0 = 0.f, rs1 = 0.f;
#pragma unroll
        for (int j = 0; j < 8; j++) {
            uint32_t u0 = f2tf(__expf(sacc[j][0]));
            uint32_t u1 = f2tf(__expf(sacc[j][1]));
            uint32_t u2 = f2tf(__expf(sacc[j][2]));
            uint32_t u3 = f2tf(__expf(sacc[j][3]));
            rs0 += __uint_as_float(u0) + __uint_as_float(u1);
            rs1 += __uint_as_float(u2) + __uint_as_float(u3);
            *(uint2*)(Pw + g * PP + j * 8 + 2 * c)       = make_uint2(u0, u1);
            *(uint2*)(Pw + (g + 8) * PP + j * 8 + 2 * c) = make_uint2(u2, u3);
        }
        rs0 += __shfl_xor_sync(0xffffffffu, rs0, 1);
        rs0 += __shfl_xor_sync(0xffffffffu, rs0, 2);
        rs1 += __shfl_xor_sync(0xffffffffu, rs1, 1);
        rs1 += __shfl_xor_sync(0xffffffffu, rs1, 2);
        lsum0 += rs0;
        lsum1 += rs1;
        __syncwarp();

        // --- O += P @ V (1xTF32, operands pre-rounded) ---
#pragma unroll
        for (int s = 0; s < 8; s++) {
            uint32_t a[4] = {
                __float_as_uint(Pw[g * PP + s * 8 + c]),
                __float_as_uint(Pw[(g + 8) * PP + s * 8 + c]),
                __float_as_uint(Pw[g * PP + s * 8 + c + 4]),
                __float_as_uint(Pw[(g + 8) * PP + s * 8 + c + 4])};
#pragma unroll
            for (int j = 0; j < 8; j++) {
                const int ba = (s * 8 + c) * VP + j * 8 + g;
                uint32_t bv[2] = {__float_as_uint(VV[ba]),
                                  __float_as_uint(VV[ba + 4 * VP])};
                mma8(oacc[j], a, bv);
            }
        }
        __syncwarp();

        if (t < SKV / 64 - 1) {
            __syncthreads();
            STS(1 - cur);
            __syncthreads();
        }
    }

    // --- epilogue: normalize, write ---
    const float i0 = 1.f / lsum0, i1 = 1.f / lsum1;
    float* o0 = Og + (size_t)(b * SQ + q0 + qi + g) * HID + head * DH;
    float* o1 = o0 + 8 * (size_t)HID;
#pragma unroll
    for (int j = 0; j < 8; j++) {
        *(float2*)(o0 + j * 8 + 2 * c) = make_float2(oacc[j][0] * i0, oacc[j][1] * i0);
        *(float2*)(o1 + j * 8 + 2 * c) = make_float2(oacc[j][2] * i1, oacc[j][3] * i1);
    }
}

// ======================================================================
extern "C" void kernel_launch(void* const* d_in, const int* in_sizes, int n_in,
                              void* d_out, int out_size)
{
    (void)in_sizes; (void)n_in; (void)out_size;
    const float* inputs = (const float*)d_in[0];
    const float* latent = (const float*)d_in[1];
    const float* wq     = (const float*)d_in[2];
    const float* wk     = (const float*)d_in[3];
    const float* wv     = (const float*)d_in[4];
    const float* wo     = (const float*)d_in[5];
    const float* qnw    = (const float*)d_in[6];
    const float* knw    = (const float*)d_in[7];
    float* out = (float*)d_out;

    float *Qb, *Kb, *Vb, *AOb;
    cudaGetSymbolAddress((void**)&Qb,  g_Q);
    cudaGetSymbolAddress((void**)&Kb,  g_K);
    cudaGetSymbolAddress((void**)&Vb,  g_V);
    cudaGetSymbolAddress((void**)&AOb, g_AO);

    const int SMG = (2 * 6912 + 256) * 4;          // 56320
    const int SMA = (2 * 8960 + 8 * 16 * 76) * 4;  // 110592
    cudaFuncSetAttribute(gemm_tc<3, true>,  cudaFuncAttributeMaxDynamicSharedMemorySize, SMG);
    cudaFuncSetAttribute(gemm_tc<1, false>, cudaFuncAttributeMaxDynamicSharedMemorySize, SMG);
    cudaFuncSetAttribute(attn_mma, cudaFuncAttributeMaxDynamicSharedMemorySize, SMA);

    dim3 blk(256);
    // Q = rmsnorm(latent @ wq^T), 3xTF32  [1024 x 1024]
    gemm_tc<3, true ><<<dim3(16, 8),  blk, SMG>>>(latent, wq, qnw, Qb, BATCH * SQ,  NH  * DH, HID);
    // K = rmsnorm(inputs @ wk^T), 3xTF32  [8192 x 256]
    gemm_tc<3, true ><<<dim3(4, 64),  blk, SMG>>>(inputs, wk, knw, Kb, BATCH * SKV, NHK * DH, HID);
    // V = inputs @ wv^T, 1xTF32           [8192 x 256]
    gemm_tc<1, false><<<dim3(4, 64),  blk, SMG>>>(inputs, wv, nullptr, Vb, BATCH * SKV, NHK * DH, HID);
    // attention
    attn_mma<<<dim3(SQ / 32, NHK, BATCH), blk, SMA>>>(Qb, Kb, Vb, AOb);
    // out = AO @ wo^T, 1xTF32             [1024 x 1024]
    gemm_tc<1, false><<<dim3(16, 8), blk, SMG>>>(AOb, wo, nullptr, out, BATCH * SQ, HID, HID);
}

// round 6
// speedup vs baseline: 1.3215x; 1.3215x over previous
#include <cuda_runtime.h>
#include <cstdint>

#define HID   1024
#define BATCH 2
#define SKV   4096
#define SQ    512
#define NH    16
#define NHK   4
#define DH    64

// ---------------- scratch ----------------
__device__ float g_Q [BATCH * SQ  * NH  * DH];
__device__ float g_K [BATCH * SKV * NHK * DH];
__device__ float g_V [BATCH * SKV * NHK * DH];
__device__ float g_AO[BATCH * SQ  * NH  * DH];

// ---------------- helpers ----------------
__device__ __forceinline__ uint32_t f2tf(float f) {
    uint32_t u;
    asm("cvt.rna.tf32.f32 %0, %1;" : "=r"(u) : "f"(f));
    return u;
}
__device__ __forceinline__ float4 f2tf4(float4 v) {
    float4 r;
    r.x = __uint_as_float(f2tf(v.x));
    r.y = __uint_as_float(f2tf(v.y));
    r.z = __uint_as_float(f2tf(v.z));
    r.w = __uint_as_float(f2tf(v.w));
    return r;
}
// pack two floats into bf16x2 (x -> low half, y -> high half), round-nearest
__device__ __forceinline__ uint32_t pack_bf(float x, float y) {
    uint32_t r;
    asm("cvt.rn.bf16x2.f32 %0, %1, %2;" : "=r"(r) : "f"(y), "f"(x));
    return r;
}
// split (x,y) into bf16x2 hi + bf16x2 lo (double-bf16)
__device__ __forceinline__ void bfsplit2(float x, float y, uint32_t& h, uint32_t& l) {
    h = pack_bf(x, y);
    float hx = __uint_as_float(h << 16);
    float hy = __uint_as_float(h & 0xffff0000u);
    l = pack_bf(x - hx, y - hy);
}
// D += A*B  (m16n8k8 tf32)
__device__ __forceinline__ void mma8(float* d, const uint32_t* a, const uint32_t* b) {
    asm volatile(
        "mma.sync.aligned.m16n8k8.row.col.f32.tf32.tf32.f32 "
        "{%0,%1,%2,%3},{%4,%5,%6,%7},{%8,%9},{%0,%1,%2,%3};"
        : "+f"(d[0]), "+f"(d[1]), "+f"(d[2]), "+f"(d[3])
        : "r"(a[0]), "r"(a[1]), "r"(a[2]), "r"(a[3]), "r"(b[0]), "r"(b[1]));
}
// D += A*B  (m16n8k16 bf16)
__device__ __forceinline__ void mma16(float* d, const uint32_t* a, const uint32_t* b) {
    asm volatile(
        "mma.sync.aligned.m16n8k16.row.col.f32.bf16.bf16.f32 "
        "{%0,%1,%2,%3},{%4,%5,%6,%7},{%8,%9},{%0,%1,%2,%3};"
        : "+f"(d[0]), "+f"(d[1]), "+f"(d[2]), "+f"(d[3])
        : "r"(a[0]), "r"(a[1]), "r"(a[2]), "r"(a[3]), "r"(b[0]), "r"(b[1]));
}

// ======================================================================
// GEMM: C[M,N] = A[M,K] @ W[N,K]^T.
// PASSES==3: 3-term double-bf16 (hi*hi + lo*hi + hi*lo), hi/lo bf16 staged
//            at STS. PASSES==1: 1xTF32, rna-rounded staged at STS.
// Double-buffered smem + register prefetch, 1 syncthreads per K-chunk.
// BM=128, BN=64, BK=32. 256 threads = 8 warps (4 M x 2 N).
// ======================================================================
template <int PASSES, bool NORM>
__global__ void __launch_bounds__(256) gemm_tc(
    const float* __restrict__ A, const float* __restrict__ W,
    const float* __restrict__ nw, float* __restrict__ C,
    int M, int N, int Kdim)
{
    extern __shared__ float sm[];
    uint32_t* smw = (uint32_t*)sm;
    // bf16 path: rows of 32 halfs, pitch 20 words (40 halfs)
    constexpr int BW = 20;
    constexpr int BUFW = (128 + 64) * 2 * BW;   // Ahi,Alo,Whi,Wlo: 7680 words
    // tf32 path: f32 rows pitch 36
    constexpr int AP = 36;
    constexpr int BUFG = (128 + 64) * AP;       // 6912 floats
    float* red = (PASSES == 3) ? (float*)(smw + 2 * BUFW) : (sm + 2 * BUFG);

    const int tid = threadIdx.x, lane = tid & 31, wid = tid >> 5;
    const int wm = wid >> 1, wn = wid & 1;
    const int g = lane >> 2, c = lane & 3;
    const int m0 = blockIdx.y * 128, n0 = blockIdx.x * 64;

    float acc[2][4][4];
#pragma unroll
    for (int mt = 0; mt < 2; mt++)
#pragma unroll
        for (int nt = 0; nt < 4; nt++)
#pragma unroll
            for (int i = 0; i < 4; i++) acc[mt][nt][i] = 0.f;

    const int arow = tid >> 1, acol = (tid & 1) * 16;
    const int wrow = tid >> 2, wcol = (tid & 3) * 8;
    const float* Ap = A + (size_t)(m0 + arow) * Kdim + acol;
    const float* Wp = W + (size_t)(n0 + wrow) * Kdim + wcol;

    float4 areg[4], wreg[2];
    auto LDGS = [&](int kt) {
#pragma unroll
        for (int i = 0; i < 4; i++) areg[i] = *(const float4*)(Ap + kt + i * 4);
#pragma unroll
        for (int i = 0; i < 2; i++) wreg[i] = *(const float4*)(Wp + kt + i * 4);
    };
    auto STSS = [&](int buf) {
        if constexpr (PASSES == 3) {
            uint32_t* Ah = smw + buf * BUFW;
            uint32_t* Al = Ah + 128 * BW;
            uint32_t* Wh = Ah + 256 * BW;
            uint32_t* Wl = Ah + 256 * BW + 64 * BW;
#pragma unroll
            for (int i = 0; i < 4; i++) {
                uint32_t h0, l0, h1, l1;
                bfsplit2(areg[i].x, areg[i].y, h0, l0);
                bfsplit2(areg[i].z, areg[i].w, h1, l1);
                const int wo = arow * BW + (acol >> 1) + 2 * i;
                Ah[wo] = h0; Ah[wo + 1] = h1;
                Al[wo] = l0; Al[wo + 1] = l1;
            }
#pragma unroll
            for (int i = 0; i < 2; i++) {
                uint32_t h0, l0, h1, l1;
                bfsplit2(wreg[i].x, wreg[i].y, h0, l0);
                bfsplit2(wreg[i].z, wreg[i].w, h1, l1);
                const int wo = wrow * BW + (wcol >> 1) + 2 * i;
                Wh[wo] = h0; Wh[wo + 1] = h1;
                Wl[wo] = l0; Wl[wo + 1] = l1;
            }
        } else {
            float* Ar = sm + buf * BUFG;
            float* Wr = Ar + 128 * AP;
#pragma unroll
            for (int i = 0; i < 4; i++)
                *(float4*)(Ar + arow * AP + acol + i * 4) = f2tf4(areg[i]);
#pragma unroll
            for (int i = 0; i < 2; i++)
                *(float4*)(Wr + wrow * AP + wcol + i * 4) = f2tf4(wreg[i]);
        }
    };

    LDGS(0); STSS(0);
    __syncthreads();

    for (int kt = 0; kt < Kdim; kt += 32) {
        const int cur = (kt >> 5) & 1;
        const bool more = (kt + 32 < Kdim);
        if (more) LDGS(kt + 32);

        if constexpr (PASSES == 3) {
            const uint32_t* Ah = smw + cur * BUFW;
            const uint32_t* Al = Ah + 128 * BW;
            const uint32_t* Wh = Ah + 256 * BW;
            const uint32_t* Wl = Ah + 256 * BW + 64 * BW;
#pragma unroll
            for (int s = 0; s < 2; s++) {
                uint32_t ah[2][4], al[2][4], bh[4][2], bl[4][2];
#pragma unroll
                for (int mt = 0; mt < 2; mt++) {
                    const int r = wm * 32 + mt * 16;
                    const int w0 = (r + g) * BW + 8 * s + c;
                    const int w1 = (r + g + 8) * BW + 8 * s + c;
                    ah[mt][0] = Ah[w0]; ah[mt][1] = Ah[w1];
                    ah[mt][2] = Ah[w0 + 4]; ah[mt][3] = Ah[w1 + 4];
                    al[mt][0] = Al[w0]; al[mt][1] = Al[w1];
                    al[mt][2] = Al[w0 + 4]; al[mt][3] = Al[w1 + 4];
                }
#pragma unroll
                for (int nt = 0; nt < 4; nt++) {
                    const int wb = (wn * 32 + nt * 8 + g) * BW + 8 * s + c;
                    bh[nt][0] = Wh[wb]; bh[nt][1] = Wh[wb + 4];
                    bl[nt][0] = Wl[wb]; bl[nt][1] = Wl[wb + 4];
                }
#pragma unroll
                for (int mt = 0; mt < 2; mt++)
#pragma unroll
                    for (int nt = 0; nt < 4; nt++) {
                        mma16(acc[mt][nt], ah[mt], bh[nt]);
                        mma16(acc[mt][nt], al[mt], bh[nt]);
                        mma16(acc[mt][nt], ah[mt], bl[nt]);
                    }
            }
        } else {
            const float* Ar = sm + cur * BUFG;
            const float* Wr = Ar + 128 * AP;
#pragma unroll
            for (int s = 0; s < 4; s++) {
                uint32_t ah[2][4], bh[4][2];
#pragma unroll
                for (int mt = 0; mt < 2; mt++) {
                    const int r = wm * 32 + mt * 16;
                    ah[mt][0] = __float_as_uint(Ar[(r + g) * AP + s * 8 + c]);
                    ah[mt][1] = __float_as_uint(Ar[(r + g + 8) * AP + s * 8 + c]);
                    ah[mt][2] = __float_as_uint(Ar[(r + g) * AP + s * 8 + c + 4]);
                    ah[mt][3] = __float_as_uint(Ar[(r + g + 8) * AP + s * 8 + c + 4]);
                }
#pragma unroll
                for (int nt = 0; nt < 4; nt++) {
                    const int n = wn * 32 + nt * 8 + g;
                    bh[nt][0] = __float_as_uint(Wr[n * AP + s * 8 + c]);
                    bh[nt][1] = __float_as_uint(Wr[n * AP + s * 8 + c + 4]);
                }
#pragma unroll
                for (int mt = 0; mt < 2; mt++)
#pragma unroll
                    for (int nt = 0; nt < 4; nt++) mma8(acc[mt][nt], ah[mt], bh[nt]);
            }
        }
        if (more) {
            STSS(1 - cur);
            __syncthreads();
        }
    }

    if (NORM) {
        __syncthreads();
        float ss0[2] = {0.f, 0.f}, ss1[2] = {0.f, 0.f};
#pragma unroll
        for (int mt = 0; mt < 2; mt++)
#pragma unroll
            for (int nt = 0; nt < 4; nt++) {
                ss0[mt] += acc[mt][nt][0] * acc[mt][nt][0] + acc[mt][nt][1] * acc[mt][nt][1];
                ss1[mt] += acc[mt][nt][2] * acc[mt][nt][2] + acc[mt][nt][3] * acc[mt][nt][3];
            }
#pragma unroll
        for (int mt = 0; mt < 2; mt++) {
            ss0[mt] += __shfl_xor_sync(0xffffffffu, ss0[mt], 1);
            ss0[mt] += __shfl_xor_sync(0xffffffffu, ss0[mt], 2);
            ss1[mt] += __shfl_xor_sync(0xffffffffu, ss1[mt], 1);
            ss1[mt] += __shfl_xor_sync(0xffffffffu, ss1[mt], 2);
            if (c == 0) {
                red[(wm * 32 + mt * 16 + g) * 2 + wn]     = ss0[mt];
                red[(wm * 32 + mt * 16 + g + 8) * 2 + wn] = ss1[mt];
            }
        }
        __syncthreads();
        float sc0[2], sc1[2];
#pragma unroll
        for (int mt = 0; mt < 2; mt++) {
            int r = (wm * 32 + mt * 16 + g) * 2;
            sc0[mt] = rsqrtf((red[r] + red[r + 1]) * (1.f / 64.f) + 1e-6f);
            r = (wm * 32 + mt * 16 + g + 8) * 2;
            sc1[mt] = rsqrtf((red[r] + red[r + 1]) * (1.f / 64.f) + 1e-6f);
        }
        float w0[4], w1[4];
#pragma unroll
        for (int nt = 0; nt < 4; nt++) {
            w0[nt] = nw[wn * 32 + nt * 8 + 2 * c];
            w1[nt] = nw[wn * 32 + nt * 8 + 2 * c + 1];
        }
#pragma unroll
        for (int mt = 0; mt < 2; mt++)
#pragma unroll
            for (int nt = 0; nt < 4; nt++) {
                acc[mt][nt][0] *= sc0[mt] * w0[nt];
                acc[mt][nt][1] *= sc0[mt] * w1[nt];
                acc[mt][nt][2] *= sc1[mt] * w0[nt];
                acc[mt][nt][3] *= sc1[mt] * w1[nt];
            }
    }

#pragma unroll
    for (int mt = 0; mt < 2; mt++)
#pragma unroll
        for (int nt = 0; nt < 4; nt++) {
            int r = m0 + wm * 32 + mt * 16 + g;
            int col = n0 + wn * 32 + nt * 8 + 2 * c;
            *(float2*)(C + (size_t)r * N + col) =
                make_float2(acc[mt][nt][0], acc[mt][nt][1]);
            *(float2*)(C + (size_t)(r + 8) * N + col) =
                make_float2(acc[mt][nt][2], acc[mt][nt][3]);
        }
}

// ======================================================================
// Attention. CTA = 128 rows (4 heads x 32 q) of one (b,hk). 8 warps.
// QK^T: 3-term double-bf16 m16n8k16; Khi/Klo bf16 staged at STS;
// Q hi/lo bf16 fragments persistent in registers.
// PV: 1xTF32, V rna-rounded at STS, P rna-rounded before sum AND store.
// No-max softmax: |s| <= 64 so exp stays finite in fp32.
// ======================================================================
__global__ void __launch_bounds__(256, 1) attn_mma(
    const float* __restrict__ Qg, const float* __restrict__ Kg,
    const float* __restrict__ Vg, float* __restrict__ Og)
{
    extern __shared__ float sm[];
    uint32_t* smw = (uint32_t*)sm;
    constexpr int KW = 36;            // words per K row (72 halfs)
    constexpr int VP = 72, PP = 76;
    constexpr int KWORDS = 64 * KW;   // 2304 words per K copy
    constexpr int BUFW = 2 * KWORDS + 64 * VP;  // 9216 words / buffer
    float* Ps = sm + 2 * BUFW;

    const int tid = threadIdx.x;
    const int lane = tid & 31, w = tid >> 5;
    const int g = lane >> 2, c = lane & 3;
    const int b = blockIdx.z, hk = blockIdx.y, q0 = blockIdx.x * 32;
    const int head = hk * 4 + (w >> 1);
    const int qi = (w & 1) * 16;

    // ---- Q fragments: double-bf16 hi/lo, 4 k16-chunks over D=64 ----
    uint32_t qh[4][4], ql[4][4];
    {
        const float* r0 = Qg + (size_t)(b * SQ + q0 + qi + g) * HID + head * DH;
        const float* r1 = r0 + 8 * (size_t)HID;
#pragma unroll
        for (int s = 0; s < 4; s++) {
            const int cs = 16 * s + 2 * c;
            bfsplit2(r0[cs],     r0[cs + 1], qh[s][0], ql[s][0]);
            bfsplit2(r1[cs],     r1[cs + 1], qh[s][1], ql[s][1]);
            bfsplit2(r0[cs + 8], r0[cs + 9], qh[s][2], ql[s][2]);
            bfsplit2(r1[cs + 8], r1[cs + 9], qh[s][3], ql[s][3]);
        }
    }

    const int krow = tid >> 2;
    const int kcol = (tid & 3) * 16;
    const float* kbase = Kg + (size_t)b * SKV * (NHK * DH) + hk * DH + kcol;
    const float* vbase = Vg + (size_t)b * SKV * (NHK * DH) + hk * DH + kcol;

    float4 kr[4], vr[4];
    auto LDG = [&](int t) {
        const float* kp = kbase + (size_t)(t * 64 + krow) * (NHK * DH);
        const float* vp = vbase + (size_t)(t * 64 + krow) * (NHK * DH);
#pragma unroll
        for (int i = 0; i < 4; i++) {
            kr[i] = *(const float4*)(kp + i * 4);
            vr[i] = *(const float4*)(vp + i * 4);
        }
    };
    auto STS = [&](int buf) {
        uint32_t* KH = smw + buf * BUFW;
        uint32_t* KL = KH + KWORDS;
        float* VV = (float*)(KH + 2 * KWORDS);
        const int wbase = krow * KW + (kcol >> 1);
#pragma unroll
        for (int i = 0; i < 4; i++) {
            uint32_t h0, l0, h1, l1;
            bfsplit2(kr[i].x, kr[i].y, h0, l0);
            bfsplit2(kr[i].z, kr[i].w, h1, l1);
            KH[wbase + 2 * i] = h0; KH[wbase + 2 * i + 1] = h1;
            KL[wbase + 2 * i] = l0; KL[wbase + 2 * i + 1] = l1;
            *(float4*)(VV + krow * VP + kcol + i * 4) = f2tf4(vr[i]);
        }
    };

    float oacc[8][4];
#pragma unroll
    for (int j = 0; j < 8; j++)
#pragma unroll
        for (int i = 0; i < 4; i++) oacc[j][i] = 0.f;
    float lsum0 = 0.f, lsum1 = 0.f;
    float* Pw = Ps + w * 16 * PP;

    LDG(0); STS(0);
    __syncthreads();

    for (int t = 0; t < SKV / 64; t++) {
        const int cur = t & 1;
        if (t < SKV / 64 - 1) LDG(t + 1);
        const uint32_t* KH = smw + cur * BUFW;
        const uint32_t* KL = KH + KWORDS;
        const float* VV = (const float*)(KH + 2 * KWORDS);

        // --- S = Q @ K^T (3-term double-bf16) ---
        float sacc[8][4];
#pragma unroll
        for (int j = 0; j < 8; j++)
#pragma unroll
            for (int i = 0; i < 4; i++) sacc[j][i] = 0.f;
#pragma unroll
        for (int s = 0; s < 4; s++) {
#pragma unroll
            for (int j = 0; j < 8; j++) {
                const int wb = (j * 8 + g) * KW + 8 * s + c;
                uint32_t bh[2] = {KH[wb], KH[wb + 4]};
                uint32_t bl[2] = {KL[wb], KL[wb + 4]};
                mma16(sacc[j], qh[s], bh);
                mma16(sacc[j], ql[s], bh);
                mma16(sacc[j], qh[s], bl);
            }
        }

        // --- P = exp(S), tf32-rounded before sum AND store ---
        float rs0 = 0.f, rs1 = 0.f;
#pragma unroll
        for (int j = 0; j < 8; j++) {
            uint32_t u0 = f2tf(__expf(sacc[j][0]));
            uint32_t u1 = f2tf(__expf(sacc[j][1]));
            uint32_t u2 = f2tf(__expf(sacc[j][2]));
            uint32_t u3 = f2tf(__expf(sacc[j][3]));
            rs0 += __uint_as_float(u0) + __uint_as_float(u1);
            rs1 += __uint_as_float(u2) + __uint_as_float(u3);
            *(uint2*)(Pw + g * PP + j * 8 + 2 * c)       = make_uint2(u0, u1);
            *(uint2*)(Pw + (g + 8) * PP + j * 8 + 2 * c) = make_uint2(u2, u3);
        }
        rs0 += __shfl_xor_sync(0xffffffffu, rs0, 1);
        rs0 += __shfl_xor_sync(0xffffffffu, rs0, 2);
        rs1 += __shfl_xor_sync(0xffffffffu, rs1, 1);
        rs1 += __shfl_xor_sync(0xffffffffu, rs1, 2);
        lsum0 += rs0;
        lsum1 += rs1;
        __syncwarp();

        // --- O += P @ V (1xTF32, operands pre-rounded) ---
#pragma unroll
        for (int s = 0; s < 8; s++) {
            uint32_t a[4] = {
                __float_as_uint(Pw[g * PP + s * 8 + c]),
                __float_as_uint(Pw[(g + 8) * PP + s * 8 + c]),
                __float_as_uint(Pw[g * PP + s * 8 + c + 4]),
                __float_as_uint(Pw[(g + 8) * PP + s * 8 + c + 4])};
#pragma unroll
            for (int j = 0; j < 8; j++) {
                const int ba = (s * 8 + c) * VP + j * 8 + g;
                uint32_t bv[2] = {__float_as_uint(VV[ba]),
                                  __float_as_uint(VV[ba + 4 * VP])};
                mma8(oacc[j], a, bv);
            }
        }
        __syncwarp();

        if (t < SKV / 64 - 1) {
            __syncthreads();
            STS(1 - cur);
            __syncthreads();
        }
    }

    // --- epilogue: normalize, write ---
    const float i0 = 1.f / lsum0, i1 = 1.f / lsum1;
    float* o0 = Og + (size_t)(b * SQ + q0 + qi + g) * HID + head * DH;
    float* o1 = o0 + 8 * (size_t)HID;
#pragma unroll
    for (int j = 0; j < 8; j++) {
        *(float2*)(o0 + j * 8 + 2 * c) = make_float2(oacc[j][0] * i0, oacc[j][1] * i0);
        *(float2*)(o1 + j * 8 + 2 * c) = make_float2(oacc[j][2] * i1, oacc[j][3] * i1);
    }
}

// ======================================================================
extern "C" void kernel_launch(void* const* d_in, const int* in_sizes, int n_in,
                              void* d_out, int out_size)
{
    (void)in_sizes; (void)n_in; (void)out_size;
    const float* inputs = (const float*)d_in[0];
    const float* latent = (const float*)d_in[1];
    const float* wq     = (const float*)d_in[2];
    const float* wk     = (const float*)d_in[3];
    const float* wv     = (const float*)d_in[4];
    const float* wo     = (const float*)d_in[5];
    const float* qnw    = (const float*)d_in[6];
    const float* knw    = (const float*)d_in[7];
    float* out = (float*)d_out;

    float *Qb, *Kb, *Vb, *AOb;
    cudaGetSymbolAddress((void**)&Qb,  g_Q);
    cudaGetSymbolAddress((void**)&Kb,  g_K);
    cudaGetSymbolAddress((void**)&Vb,  g_V);
    cudaGetSymbolAddress((void**)&AOb, g_AO);

    const int SMG3 = (2 * 7680 + 256) * 4;          // 62464: bf16 3-pass GEMM
    const int SMG1 = (2 * 6912 + 256) * 4;          // 56320: tf32 1-pass GEMM
    const int SMA  = (2 * 9216 + 8 * 16 * 76) * 4;  // 112640: attention
    cudaFuncSetAttribute(gemm_tc<3, true>,  cudaFuncAttributeMaxDynamicSharedMemorySize, SMG3);
    cudaFuncSetAttribute(gemm_tc<1, false>, cudaFuncAttributeMaxDynamicSharedMemorySize, SMG1);
    cudaFuncSetAttribute(attn_mma, cudaFuncAttributeMaxDynamicSharedMemorySize, SMA);

    dim3 blk(256);
    // Q = rmsnorm(latent @ wq^T), 3x double-bf16  [1024 x 1024]
    gemm_tc<3, true ><<<dim3(16, 8),  blk, SMG3>>>(latent, wq, qnw, Qb, BATCH * SQ,  NH  * DH, HID);
    // K = rmsnorm(inputs @ wk^T), 3x double-bf16  [8192 x 256]
    gemm_tc<3, true ><<<dim3(4, 64),  blk, SMG3>>>(inputs, wk, knw, Kb, BATCH * SKV, NHK * DH, HID);
    // V = inputs @ wv^T, 1xTF32                   [8192 x 256]
    gemm_tc<1, false><<<dim3(4, 64),  blk, SMG1>>>(inputs, wv, nullptr, Vb, BATCH * SKV, NHK * DH, HID);
    // attention
    attn_mma<<<dim3(SQ / 32, NHK, BATCH), blk, SMA>>>(Qb, Kb, Vb, AOb);
    // out = AO @ wo^T, 1xTF32                     [1024 x 1024]
    gemm_tc<1, false><<<dim3(16, 8), blk, SMG1>>>(AOb, wo, nullptr, out, BATCH * SQ, HID, HID);
}

// round 7
// speedup vs baseline: 1.4652x; 1.1087x over previous
#include <cuda_runtime.h>
#include <cstdint>

#define HID   1024
#define BATCH 2
#define SKV   4096
#define SQ    512
#define NH    16
#define NHK   4
#define DH    64

// ---------------- scratch ----------------
__device__ float g_Q [BATCH * SQ  * NH  * DH];
__device__ float g_K [BATCH * SKV * NHK * DH];
__device__ float g_V [BATCH * SKV * NHK * DH];
__device__ float g_AO[BATCH * SQ  * NH  * DH];

// ---------------- helpers ----------------
__device__ __forceinline__ uint32_t f2tf(float f) {
    uint32_t u;
    asm("cvt.rna.tf32.f32 %0, %1;" : "=r"(u) : "f"(f));
    return u;
}
__device__ __forceinline__ float4 f2tf4(float4 v) {
    float4 r;
    r.x = __uint_as_float(f2tf(v.x));
    r.y = __uint_as_float(f2tf(v.y));
    r.z = __uint_as_float(f2tf(v.z));
    r.w = __uint_as_float(f2tf(v.w));
    return r;
}
// pack two floats into bf16x2 (x -> low half, y -> high half), round-nearest
__device__ __forceinline__ uint32_t pack_bf(float x, float y) {
    uint32_t r;
    asm("cvt.rn.bf16x2.f32 %0, %1, %2;" : "=r"(r) : "f"(y), "f"(x));
    return r;
}
// split (x,y) into bf16x2 hi + bf16x2 lo (double-bf16)
__device__ __forceinline__ void bfsplit2(float x, float y, uint32_t& h, uint32_t& l) {
    h = pack_bf(x, y);
    float hx = __uint_as_float(h << 16);
    float hy = __uint_as_float(h & 0xffff0000u);
    l = pack_bf(x - hx, y - hy);
}
// D += A*B  (m16n8k8 tf32)
__device__ __forceinline__ void mma8(float* d, const uint32_t* a, const uint32_t* b) {
    asm volatile(
        "mma.sync.aligned.m16n8k8.row.col.f32.tf32.tf32.f32 "
        "{%0,%1,%2,%3},{%4,%5,%6,%7},{%8,%9},{%0,%1,%2,%3};"
        : "+f"(d[0]), "+f"(d[1]), "+f"(d[2]), "+f"(d[3])
        : "r"(a[0]), "r"(a[1]), "r"(a[2]), "r"(a[3]), "r"(b[0]), "r"(b[1]));
}
// D += A*B  (m16n8k16 bf16)
__device__ __forceinline__ void mma16(float* d, const uint32_t* a, const uint32_t* b) {
    asm volatile(
        "mma.sync.aligned.m16n8k16.row.col.f32.bf16.bf16.f32 "
        "{%0,%1,%2,%3},{%4,%5,%6,%7},{%8,%9},{%0,%1,%2,%3};"
        : "+f"(d[0]), "+f"(d[1]), "+f"(d[2]), "+f"(d[3])
        : "r"(a[0]), "r"(a[1]), "r"(a[2]), "r"(a[3]), "r"(b[0]), "r"(b[1]));
}
__device__ __forceinline__ uint32_t smem_u32(const void* p) {
    uint32_t a;
    asm("{ .reg .u64 t; cvta.to.shared.u64 t, %1; cvt.u32.u64 %0, t; }" : "=r"(a) : "l"(p));
    return a;
}
__device__ __forceinline__ void ldsm4(uint32_t* r, uint32_t addr) {
    asm volatile("ldmatrix.sync.aligned.m8n8.x4.shared.b16 {%0,%1,%2,%3}, [%4];"
        : "=r"(r[0]), "=r"(r[1]), "=r"(r[2]), "=r"(r[3]) : "r"(addr));
}
__device__ __forceinline__ void ldsm4t(uint32_t* r, uint32_t addr) {
    asm volatile("ldmatrix.sync.aligned.m8n8.x4.trans.shared.b16 {%0,%1,%2,%3}, [%4];"
        : "=r"(r[0]), "=r"(r[1]), "=r"(r[2]), "=r"(r[3]) : "r"(addr));
}

// ======================================================================
// GEMM (unchanged from R6): C = A @ W^T.
// PASSES==3: 3-term double-bf16; PASSES==1: 1xTF32 rna-rounded at STS.
// ======================================================================
template <int PASSES, bool NORM>
__global__ void __launch_bounds__(256) gemm_tc(
    const float* __restrict__ A, const float* __restrict__ W,
    const float* __restrict__ nw, float* __restrict__ C,
    int M, int N, int Kdim)
{
    extern __shared__ float sm[];
    uint32_t* smw = (uint32_t*)sm;
    constexpr int BW = 20;
    constexpr int BUFW = (128 + 64) * 2 * BW;
    constexpr int AP = 36;
    constexpr int BUFG = (128 + 64) * AP;
    float* red = (PASSES == 3) ? (float*)(smw + 2 * BUFW) : (sm + 2 * BUFG);

    const int tid = threadIdx.x, lane = tid & 31, wid = tid >> 5;
    const int wm = wid >> 1, wn = wid & 1;
    const int g = lane >> 2, c = lane & 3;
    const int m0 = blockIdx.y * 128, n0 = blockIdx.x * 64;

    float acc[2][4][4];
#pragma unroll
    for (int mt = 0; mt < 2; mt++)
#pragma unroll
        for (int nt = 0; nt < 4; nt++)
#pragma unroll
            for (int i = 0; i < 4; i++) acc[mt][nt][i] = 0.f;

    const int arow = tid >> 1, acol = (tid & 1) * 16;
    const int wrow = tid >> 2, wcol = (tid & 3) * 8;
    const float* Ap = A + (size_t)(m0 + arow) * Kdim + acol;
    const float* Wp = W + (size_t)(n0 + wrow) * Kdim + wcol;

    float4 areg[4], wreg[2];
    auto LDGS = [&](int kt) {
#pragma unroll
        for (int i = 0; i < 4; i++) areg[i] = *(const float4*)(Ap + kt + i * 4);
#pragma unroll
        for (int i = 0; i < 2; i++) wreg[i] = *(const float4*)(Wp + kt + i * 4);
    };
    auto STSS = [&](int buf) {
        if constexpr (PASSES == 3) {
            uint32_t* Ah = smw + buf * BUFW;
            uint32_t* Al = Ah + 128 * BW;
            uint32_t* Wh = Ah + 256 * BW;
            uint32_t* Wl = Ah + 256 * BW + 64 * BW;
#pragma unroll
            for (int i = 0; i < 4; i++) {
                uint32_t h0, l0, h1, l1;
                bfsplit2(areg[i].x, areg[i].y, h0, l0);
                bfsplit2(areg[i].z, areg[i].w, h1, l1);
                const int wo = arow * BW + (acol >> 1) + 2 * i;
                Ah[wo] = h0; Ah[wo + 1] = h1;
                Al[wo] = l0; Al[wo + 1] = l1;
            }
#pragma unroll
            for (int i = 0; i < 2; i++) {
                uint32_t h0, l0, h1, l1;
                bfsplit2(wreg[i].x, wreg[i].y, h0, l0);
                bfsplit2(wreg[i].z, wreg[i].w, h1, l1);
                const int wo = wrow * BW + (wcol >> 1) + 2 * i;
                Wh[wo] = h0; Wh[wo + 1] = h1;
                Wl[wo] = l0; Wl[wo + 1] = l1;
            }
        } else {
            float* Ar = sm + buf * BUFG;
            float* Wr = Ar + 128 * AP;
#pragma unroll
            for (int i = 0; i < 4; i++)
                *(float4*)(Ar + arow * AP + acol + i * 4) = f2tf4(areg[i]);
#pragma unroll
            for (int i = 0; i < 2; i++)
                *(float4*)(Wr + wrow * AP + wcol + i * 4) = f2tf4(wreg[i]);
        }
    };

    LDGS(0); STSS(0);
    __syncthreads();

    for (int kt = 0; kt < Kdim; kt += 32) {
        const int cur = (kt >> 5) & 1;
        const bool more = (kt + 32 < Kdim);
        if (more) LDGS(kt + 32);

        if constexpr (PASSES == 3) {
            const uint32_t* Ah = smw + cur * BUFW;
            const uint32_t* Al = Ah + 128 * BW;
            const uint32_t* Wh = Ah + 256 * BW;
            const uint32_t* Wl = Ah + 256 * BW + 64 * BW;
#pragma unroll
            for (int s = 0; s < 2; s++) {
                uint32_t ah[2][4], al[2][4], bh[4][2], bl[4][2];
#pragma unroll
                for (int mt = 0; mt < 2; mt++) {
                    const int r = wm * 32 + mt * 16;
                    const int w0 = (r + g) * BW + 8 * s + c;
                    const int w1 = (r + g + 8) * BW + 8 * s + c;
                    ah[mt][0] = Ah[w0]; ah[mt][1] = Ah[w1];
                    ah[mt][2] = Ah[w0 + 4]; ah[mt][3] = Ah[w1 + 4];
                    al[mt][0] = Al[w0]; al[mt][1] = Al[w1];
                    al[mt][2] = Al[w0 + 4]; al[mt][3] = Al[w1 + 4];
                }
#pragma unroll
                for (int nt = 0; nt < 4; nt++) {
                    const int wb = (wn * 32 + nt * 8 + g) * BW + 8 * s + c;
                    bh[nt][0] = Wh[wb]; bh[nt][1] = Wh[wb + 4];
                    bl[nt][0] = Wl[wb]; bl[nt][1] = Wl[wb + 4];
                }
#pragma unroll
                for (int mt = 0; mt < 2; mt++)
#pragma unroll
                    for (int nt = 0; nt < 4; nt++) {
                        mma16(acc[mt][nt], ah[mt], bh[nt]);
                        mma16(acc[mt][nt], al[mt], bh[nt]);
                        mma16(acc[mt][nt], ah[mt], bl[nt]);
                    }
            }
        } else {
            const float* Ar = sm + cur * BUFG;
            const float* Wr = Ar + 128 * AP;
#pragma unroll
            for (int s = 0; s < 4; s++) {
                uint32_t ah[2][4], bh[4][2];
#pragma unroll
                for (int mt = 0; mt < 2; mt++) {
                    const int r = wm * 32 + mt * 16;
                    ah[mt][0] = __float_as_uint(Ar[(r + g) * AP + s * 8 + c]);
                    ah[mt][1] = __float_as_uint(Ar[(r + g + 8) * AP + s * 8 + c]);
                    ah[mt][2] = __float_as_uint(Ar[(r + g) * AP + s * 8 + c + 4]);
                    ah[mt][3] = __float_as_uint(Ar[(r + g + 8) * AP + s * 8 + c + 4]);
                }
#pragma unroll
                for (int nt = 0; nt < 4; nt++) {
                    const int n = wn * 32 + nt * 8 + g;
                    bh[nt][0] = __float_as_uint(Wr[n * AP + s * 8 + c]);
                    bh[nt][1] = __float_as_uint(Wr[n * AP + s * 8 + c + 4]);
                }
#pragma unroll
                for (int mt = 0; mt < 2; mt++)
#pragma unroll
                    for (int nt = 0; nt < 4; nt++) mma8(acc[mt][nt], ah[mt], bh[nt]);
            }
        }
        if (more) {
            STSS(1 - cur);
            __syncthreads();
        }
    }

    if (NORM) {
        __syncthreads();
        float ss0[2] = {0.f, 0.f}, ss1[2] = {0.f, 0.f};
#pragma unroll
        for (int mt = 0; mt < 2; mt++)
#pragma unroll
            for (int nt = 0; nt < 4; nt++) {
                ss0[mt] += acc[mt][nt][0] * acc[mt][nt][0] + acc[mt][nt][1] * acc[mt][nt][1];
                ss1[mt] += acc[mt][nt][2] * acc[mt][nt][2] + acc[mt][nt][3] * acc[mt][nt][3];
            }
#pragma unroll
        for (int mt = 0; mt < 2; mt++) {
            ss0[mt] += __shfl_xor_sync(0xffffffffu, ss0[mt], 1);
            ss0[mt] += __shfl_xor_sync(0xffffffffu, ss0[mt], 2);
            ss1[mt] += __shfl_xor_sync(0xffffffffu, ss1[mt], 1);
            ss1[mt] += __shfl_xor_sync(0xffffffffu, ss1[mt], 2);
            if (c == 0) {
                red[(wm * 32 + mt * 16 + g) * 2 + wn]     = ss0[mt];
                red[(wm * 32 + mt * 16 + g + 8) * 2 + wn] = ss1[mt];
            }
        }
        __syncthreads();
        float sc0[2], sc1[2];
#pragma unroll
        for (int mt = 0; mt < 2; mt++) {
            int r = (wm * 32 + mt * 16 + g) * 2;
            sc0[mt] = rsqrtf((red[r] + red[r + 1]) * (1.f / 64.f) + 1e-6f);
            r = (wm * 32 + mt * 16 + g + 8) * 2;
            sc1[mt] = rsqrtf((red[r] + red[r + 1]) * (1.f / 64.f) + 1e-6f);
        }
        float w0[4], w1[4];
#pragma unroll
        for (int nt = 0; nt < 4; nt++) {
            w0[nt] = nw[wn * 32 + nt * 8 + 2 * c];
            w1[nt] = nw[wn * 32 + nt * 8 + 2 * c + 1];
        }
#pragma unroll
        for (int mt = 0; mt < 2; mt++)
#pragma unroll
            for (int nt = 0; nt < 4; nt++) {
                acc[mt][nt][0] *= sc0[mt] * w0[nt];
                acc[mt][nt][1] *= sc0[mt] * w1[nt];
                acc[mt][nt][2] *= sc1[mt] * w0[nt];
                acc[mt][nt][3] *= sc1[mt] * w1[nt];
            }
    }

#pragma unroll
    for (int mt = 0; mt < 2; mt++)
#pragma unroll
        for (int nt = 0; nt < 4; nt++) {
            int r = m0 + wm * 32 + mt * 16 + g;
            int col = n0 + wn * 32 + nt * 8 + 2 * c;
            *(float2*)(C + (size_t)r * N + col) =
                make_float2(acc[mt][nt][0], acc[mt][nt][1]);
            *(float2*)(C + (size_t)(r + 8) * N + col) =
                make_float2(acc[mt][nt][2], acc[mt][nt][3]);
        }
}

// ======================================================================
// Attention v2 (FA2 dataflow). CTA = 128 rows (4 heads x 32 q), 8 warps.
// QK^T: 3-term double-bf16, K hi/lo via ldmatrix.x4.
// P: exp in fp32, split to bf16 hi/lo A-fragments IN REGISTERS (the
//    m16n8 C layout == m16n8k16 A layout after pair-packing).
// PV: 3-term double-bf16, V hi/lo via ldmatrix.x4.trans. No P smem.
// ======================================================================
__global__ void __launch_bounds__(256, 1) attn_mma(
    const float* __restrict__ Qg, const float* __restrict__ Kg,
    const float* __restrict__ Vg, float* __restrict__ Og)
{
    extern __shared__ char smc[];
    constexpr int PW = 36;                 // words per row (72 halfs = 144B)
    constexpr int TILE_W = 64 * PW;        // 2304 words per matrix copy
    constexpr int BUFW = 4 * TILE_W;       // KH,KL,VH,VL = 9216 words
    uint32_t* smw = (uint32_t*)smc;
    const uint32_t sbase = smem_u32(smc);

    const int tid = threadIdx.x;
    const int lane = tid & 31, w = tid >> 5;
    const int g = lane >> 2, c = lane & 3;
    const int r8 = lane & 7, mm = lane >> 3;   // ldmatrix row / matrix idx
    const int b = blockIdx.z, hk = blockIdx.y, q0 = blockIdx.x * 32;
    const int head = hk * 4 + (w >> 1);
    const int qi = (w & 1) * 16;

    // ---- Q fragments: double-bf16 hi/lo, 4 k16-chunks over D=64 ----
    uint32_t qh[4][4], ql[4][4];
    {
        const float* r0 = Qg + (size_t)(b * SQ + q0 + qi + g) * HID + head * DH;
        const float* r1 = r0 + 8 * (size_t)HID;
#pragma unroll
        for (int s = 0; s < 4; s++) {
            const int cs = 16 * s + 2 * c;
            bfsplit2(r0[cs],     r0[cs + 1], qh[s][0], ql[s][0]);
            bfsplit2(r1[cs],     r1[cs + 1], qh[s][1], ql[s][1]);
            bfsplit2(r0[cs + 8], r0[cs + 9], qh[s][2], ql[s][2]);
            bfsplit2(r1[cs + 8], r1[cs + 9], qh[s][3], ql[s][3]);
        }
    }

    const int krow = tid >> 2;
    const int kcol = (tid & 3) * 16;
    const float* kbase = Kg + (size_t)b * SKV * (NHK * DH) + hk * DH + kcol;
    const float* vbase = Vg + (size_t)b * SKV * (NHK * DH) + hk * DH + kcol;

    float4 kr[4], vr[4];
    auto LDG = [&](int t) {
        const float* kp = kbase + (size_t)(t * 64 + krow) * (NHK * DH);
        const float* vp = vbase + (size_t)(t * 64 + krow) * (NHK * DH);
#pragma unroll
        for (int i = 0; i < 4; i++) {
            kr[i] = *(const float4*)(kp + i * 4);
            vr[i] = *(const float4*)(vp + i * 4);
        }
    };
    auto STS = [&](int buf) {
        uint32_t* KH = smw + buf * BUFW;
        uint32_t* KL = KH + TILE_W;
        uint32_t* VH = KH + 2 * TILE_W;
        uint32_t* VL = KH + 3 * TILE_W;
        const int wb = krow * PW + (kcol >> 1);
#pragma unroll
        for (int i = 0; i < 4; i++) {
            uint32_t h0, l0, h1, l1;
            bfsplit2(kr[i].x, kr[i].y, h0, l0);
            bfsplit2(kr[i].z, kr[i].w, h1, l1);
            KH[wb + 2 * i] = h0; KH[wb + 2 * i + 1] = h1;
            KL[wb + 2 * i] = l0; KL[wb + 2 * i + 1] = l1;
            bfsplit2(vr[i].x, vr[i].y, h0, l0);
            bfsplit2(vr[i].z, vr[i].w, h1, l1);
            VH[wb + 2 * i] = h0; VH[wb + 2 * i + 1] = h1;
            VL[wb + 2 * i] = l0; VL[wb + 2 * i + 1] = l1;
        }
    };

    float oacc[8][4];
#pragma unroll
    for (int j = 0; j < 8; j++)
#pragma unroll
        for (int i = 0; i < 4; i++) oacc[j][i] = 0.f;
    float lsum0 = 0.f, lsum1 = 0.f;

    // per-thread ldmatrix byte offsets (within a matrix copy)
    const uint32_t k_off = (uint32_t)r8 * 144u + (uint32_t)mm * 16u;       // non-trans
    const uint32_t v_off = ((uint32_t)(8 * (mm & 1) + r8)) * 144u + (uint32_t)(mm >> 1) * 16u; // trans

    LDG(0); STS(0);
    __syncthreads();

    for (int t = 0; t < SKV / 64; t++) {
        const int cur = t & 1;
        if (t < SKV / 64 - 1) LDG(t + 1);
        const uint32_t kh_b = sbase + (uint32_t)(cur * BUFW) * 4u;
        const uint32_t kl_b = kh_b + TILE_W * 4u;
        const uint32_t vh_b = kh_b + 2u * TILE_W * 4u;
        const uint32_t vl_b = kh_b + 3u * TILE_W * 4u;

        // --- S = Q @ K^T (3-term double-bf16, K frags via ldmatrix) ---
        float sacc[8][4];
#pragma unroll
        for (int j = 0; j < 8; j++) {
            const uint32_t ro = (uint32_t)(8 * j) * 144u;
            uint32_t kh[8], kl[8];
            ldsm4(kh,     kh_b + ro + k_off);
            ldsm4(kh + 4, kh_b + ro + k_off + 64u);
            ldsm4(kl,     kl_b + ro + k_off);
            ldsm4(kl + 4, kl_b + ro + k_off + 64u);
#pragma unroll
            for (int i = 0; i < 4; i++) sacc[j][i] = 0.f;
#pragma unroll
            for (int s = 0; s < 4; s++) {
                mma16(sacc[j], qh[s], kh + 2 * s);
                mma16(sacc[j], ql[s], kh + 2 * s);
                mma16(sacc[j], qh[s], kl + 2 * s);
            }
        }

        // --- P = exp(S): fp32 row-sum, pack to bf16 hi/lo A-frags in regs ---
        uint32_t pah[4][4], pal[4][4];
        float rs0 = 0.f, rs1 = 0.f;
#pragma unroll
        for (int j = 0; j < 8; j++) {
            float p0 = __expf(sacc[j][0]);
            float p1 = __expf(sacc[j][1]);
            float p2 = __expf(sacc[j][2]);
            float p3 = __expf(sacc[j][3]);
            rs0 += p0 + p1;
            rs1 += p2 + p3;
            const int s = j >> 1, o = (j & 1) * 2;
            bfsplit2(p0, p1, pah[s][o],     pal[s][o]);
            bfsplit2(p2, p3, pah[s][o + 1], pal[s][o + 1]);
        }
        rs0 += __shfl_xor_sync(0xffffffffu, rs0, 1);
        rs0 += __shfl_xor_sync(0xffffffffu, rs0, 2);
        rs1 += __shfl_xor_sync(0xffffffffu, rs1, 1);
        rs1 += __shfl_xor_sync(0xffffffffu, rs1, 2);
        lsum0 += rs0;
        lsum1 += rs1;

        // --- O += P @ V (3-term double-bf16, V frags via ldmatrix.trans) ---
#pragma unroll
        for (int s = 0; s < 4; s++) {
            const uint32_t so = (uint32_t)(16 * s) * 144u;
#pragma unroll
            for (int jj = 0; jj < 4; jj++) {
                const uint32_t co = so + (uint32_t)(32 * jj) + v_off;
                uint32_t vh[4], vl[4];
                ldsm4t(vh, vh_b + co);
                ldsm4t(vl, vl_b + co);
                mma16(oacc[2 * jj],     pah[s], vh);
                mma16(oacc[2 * jj],     pal[s], vh);
                mma16(oacc[2 * jj],     pah[s], vl);
                mma16(oacc[2 * jj + 1], pah[s], vh + 2);
                mma16(oacc[2 * jj + 1], pal[s], vh + 2);
                mma16(oacc[2 * jj + 1], pah[s], vl + 2);
            }
        }

        if (t < SKV / 64 - 1) {
            __syncthreads();
            STS(1 - cur);
            __syncthreads();
        }
    }

    // --- epilogue: normalize, write ---
    const float i0 = 1.f / lsum0, i1 = 1.f / lsum1;
    float* o0 = Og + (size_t)(b * SQ + q0 + qi + g) * HID + head * DH;
    float* o1 = o0 + 8 * (size_t)HID;
#pragma unroll
    for (int j = 0; j < 8; j++) {
        *(float2*)(o0 + j * 8 + 2 * c) = make_float2(oacc[j][0] * i0, oacc[j][1] * i0);
        *(float2*)(o1 + j * 8 + 2 * c) = make_float2(oacc[j][2] * i1, oacc[j][3] * i1);
    }
}

// ======================================================================
extern "C" void kernel_launch(void* const* d_in, const int* in_sizes, int n_in,
                              void* d_out, int out_size)
{
    (void)in_sizes; (void)n_in; (void)out_size;
    const float* inputs = (const float*)d_in[0];
    const float* latent = (const float*)d_in[1];
    const float* wq     = (const float*)d_in[2];
    const float* wk     = (const float*)d_in[3];
    const float* wv     = (const float*)d_in[4];
    const float* wo     = (const float*)d_in[5];
    const float* qnw    = (const float*)d_in[6];
    const float* knw    = (const float*)d_in[7];
    float* out = (float*)d_out;

    float *Qb, *Kb, *Vb, *AOb;
    cudaGetSymbolAddress((void**)&Qb,  g_Q);
    cudaGetSymbolAddress((void**)&Kb,  g_K);
    cudaGetSymbolAddress((void**)&Vb,  g_V);
    cudaGetSymbolAddress((void**)&AOb, g_AO);

    const int SMG3 = (2 * 7680 + 256) * 4;   // 62464: bf16 3-pass GEMM
    const int SMG1 = (2 * 6912 + 256) * 4;   // 56320: tf32 1-pass GEMM
    const int SMA  = 2 * 4 * 2304 * 4;       // 73728: attention (KH,KL,VH,VL x2)
    cudaFuncSetAttribute(gemm_tc<3, true>,  cudaFuncAttributeMaxDynamicSharedMemorySize, SMG3);
    cudaFuncSetAttribute(gemm_tc<1, false>, cudaFuncAttributeMaxDynamicSharedMemorySize, SMG1);
    cudaFuncSetAttribute(attn_mma, cudaFuncAttributeMaxDynamicSharedMemorySize, SMA);

    dim3 blk(256);
    // Q = rmsnorm(latent @ wq^T), 3x double-bf16  [1024 x 1024]
    gemm_tc<3, true ><<<dim3(16, 8),  blk, SMG3>>>(latent, wq, qnw, Qb, BATCH * SQ,  NH  * DH, HID);
    // K = rmsnorm(inputs @ wk^T), 3x double-bf16  [8192 x 256]
    gemm_tc<3, true ><<<dim3(4, 64),  blk, SMG3>>>(inputs, wk, knw, Kb, BATCH * SKV, NHK * DH, HID);
    // V = inputs @ wv^T, 1xTF32                   [8192 x 256]
    gemm_tc<1, false><<<dim3(4, 64),  blk, SMG1>>>(inputs, wv, nullptr, Vb, BATCH * SKV, NHK * DH, HID);
    // attention
    attn_mma<<<dim3(SQ / 32, NHK, BATCH), blk, SMA>>>(Qb, Kb, Vb, AOb);
    // out = AO @ wo^T, 1xTF32                     [1024 x 1024]
    gemm_tc<1, false><<<dim3(16, 8), blk, SMG1>>>(AOb, wo, nullptr, out, BATCH * SQ, HID, HID);
}

// round 10
// speedup vs baseline: 1.5418x; 1.0523x over previous
#include <cuda_runtime.h>
#include <cstdint>

#define HID   1024
#define BATCH 2
#define SKV   4096
#define SQ    512
#define NH    16
#define NHK   4
#define DH    64

// ---------------- scratch ----------------
__device__ float g_Q [BATCH * SQ  * NH  * DH];
__device__ float g_K [BATCH * SKV * NHK * DH];
__device__ float g_V [BATCH * SKV * NHK * DH];
// pre-split bf16 hi/lo operand buffers (uint4 => 16B-aligned, required for
// the 128-bit loads in gemm_bf3)
__device__ uint4 g_inh [8192 * 1024 / 8], g_inl [8192 * 1024 / 8];
__device__ uint4 g_lath[1024 * 1024 / 8], g_latl[1024 * 1024 / 8];
__device__ uint4 g_wqh [1024 * 1024 / 8], g_wql [1024 * 1024 / 8];
__device__ uint4 g_wkh [ 256 * 1024 / 8], g_wkl [ 256 * 1024 / 8];
__device__ uint4 g_wvh [ 256 * 1024 / 8], g_wvl [ 256 * 1024 / 8];
__device__ uint4 g_woh [1024 * 1024 / 8], g_wol [1024 * 1024 / 8];
// AO buffers MUST be uint4 (16B aligned): consumed by 128-bit loads in gemm.
__device__ uint4 g_AOh[1024 * 512 / 4], g_AOl[1024 * 512 / 4];

// ---------------- helpers ----------------
__device__ __forceinline__ uint32_t pack_bf(float x, float y) {
    uint32_t r;
    asm("cvt.rn.bf16x2.f32 %0, %1, %2;" : "=r"(r) : "f"(y), "f"(x));
    return r;
}
__device__ __forceinline__ void bfsplit2(float x, float y, uint32_t& h, uint32_t& l) {
    h = pack_bf(x, y);
    float hx = __uint_as_float(h << 16);
    float hy = __uint_as_float(h & 0xffff0000u);
    l = pack_bf(x - hx, y - hy);
}
__device__ __forceinline__ void mma16(float* d, const uint32_t* a, const uint32_t* b) {
    asm volatile(
        "mma.sync.aligned.m16n8k16.row.col.f32.bf16.bf16.f32 "
        "{%0,%1,%2,%3},{%4,%5,%6,%7},{%8,%9},{%0,%1,%2,%3};"
        : "+f"(d[0]), "+f"(d[1]), "+f"(d[2]), "+f"(d[3])
        : "r"(a[0]), "r"(a[1]), "r"(a[2]), "r"(a[3]), "r"(b[0]), "r"(b[1]));
}
__device__ __forceinline__ uint32_t smem_u32(const void* p) {
    uint32_t a;
    asm("{ .reg .u64 t; cvta.to.shared.u64 t, %1; cvt.u32.u64 %0, t; }" : "=r"(a) : "l"(p));
    return a;
}
__device__ __forceinline__ void ldsm4(uint32_t* r, uint32_t addr) {
    asm volatile("ldmatrix.sync.aligned.m8n8.x4.shared.b16 {%0,%1,%2,%3}, [%4];"
        : "=r"(r[0]), "=r"(r[1]), "=r"(r[2]), "=r"(r[3]) : "r"(addr));
}
__device__ __forceinline__ void ldsm4t(uint32_t* r, uint32_t addr) {
    asm volatile("ldmatrix.sync.aligned.m8n8.x4.trans.shared.b16 {%0,%1,%2,%3}, [%4];"
        : "=r"(r[0]), "=r"(r[1]), "=r"(r[2]), "=r"(r[3]) : "r"(addr));
}

// ======================================================================
// presplit: X (f32) -> Xh, Xl (bf16 halfs, same layout)
// ======================================================================
__global__ void presplit(const float4* __restrict__ x,
                         uint4* __restrict__ h, uint4* __restrict__ l, int n8)
{
    int i = blockIdx.x * blockDim.x + threadIdx.x;
    if (i >= n8) return;
    float4 v0 = x[2 * i], v1 = x[2 * i + 1];
    uint4 H, L;
    bfsplit2(v0.x, v0.y, H.x, L.x);
    bfsplit2(v0.z, v0.w, H.y, L.y);
    bfsplit2(v1.x, v1.y, H.z, L.z);
    bfsplit2(v1.z, v1.w, H.w, L.w);
    h[i] = H; l[i] = L;
}

// ======================================================================
// gemm_bf3: C[M,N] = A[M,K] @ W[N,K]^T, 3-term double-bf16.
// Pre-split bf16 operands, register-prefetch LDG -> STS double buffering,
// ldmatrix fragment loads. BM=128, BN=64, BK=32, 8 warps.
// Row pitch 80B -> conflict-free ldsm.
// ======================================================================
template <bool NORM>
__global__ void __launch_bounds__(256, 2) gemm_bf3(
    const uint16_t* __restrict__ Ah, const uint16_t* __restrict__ Al,
    const uint16_t* __restrict__ Wh, const uint16_t* __restrict__ Wl,
    const float* __restrict__ nw, float* __restrict__ C,
    int M, int N, int Kdim)
{
    extern __shared__ char smc[];
    const uint32_t sb = smem_u32(smc);
    constexpr int STAGE = 30720;         // Ah(10240)+Al(10240)+Wh(5120)+Wl(5120)
    constexpr int O_AL = 10240, O_WH = 20480, O_WL = 25600;
    float* red = (float*)(smc + 2 * STAGE);

    const int tid = threadIdx.x, lane = tid & 31, wid = tid >> 5;
    const int wm = wid >> 1, wn = wid & 1;
    const int g = lane >> 2, c = lane & 3;
    const int m0 = blockIdx.y * 128, n0 = blockIdx.x * 64;

    float acc[2][4][4];
#pragma unroll
    for (int mt = 0; mt < 2; mt++)
#pragma unroll
        for (int nt = 0; nt < 4; nt++)
#pragma unroll
            for (int i = 0; i < 4; i++) acc[mt][nt][i] = 0.f;

    // staging assignment: row = tid>>2 (0..63), chunk = tid&3 (16B each)
    const int srow = tid >> 2, sch = tid & 3;
    const size_t abase0 = (size_t)(m0 + srow) * Kdim + sch * 8;
    const size_t abase1 = (size_t)(m0 + srow + 64) * Kdim + sch * 8;
    const size_t wbase  = (size_t)(n0 + srow) * Kdim + sch * 8;
    const int ro = srow * 80 + sch * 16;

    uint4 rAh0, rAh1, rAl0, rAl1, rWh, rWl;
    auto LDGS = [&](int kt) {
        rAh0 = *(const uint4*)(Ah + abase0 + kt);
        rAh1 = *(const uint4*)(Ah + abase1 + kt);
        rAl0 = *(const uint4*)(Al + abase0 + kt);
        rAl1 = *(const uint4*)(Al + abase1 + kt);
        rWh  = *(const uint4*)(Wh + wbase + kt);
        rWl  = *(const uint4*)(Wl + wbase + kt);
    };
    auto STSS = [&](int buf) {
        char* d = smc + buf * STAGE;
        *(uint4*)(d + ro)                  = rAh0;
        *(uint4*)(d + 64 * 80 + ro)        = rAh1;
        *(uint4*)(d + O_AL + ro)           = rAl0;
        *(uint4*)(d + O_AL + 64 * 80 + ro) = rAl1;
        *(uint4*)(d + O_WH + ro)           = rWh;
        *(uint4*)(d + O_WL + ro)           = rWl;
    };

    const uint32_t aoff = (uint32_t)((wm * 32 + (lane & 7) + ((lane >> 3) & 1) * 8) * 80
                                     + ((lane >> 4) & 1) * 16);
    const uint32_t boff = (uint32_t)((wn * 32 + (lane & 7) + ((lane >> 4) & 1) * 8) * 80
                                     + ((lane >> 3) & 1) * 16);

    LDGS(0); STSS(0);
    __syncthreads();

    for (int kt = 0; kt < Kdim; kt += 32) {
        const int buf = (kt >> 5) & 1;
        const bool more = (kt + 32 < Kdim);
        if (more) LDGS(kt + 32);

        const uint32_t base = sb + buf * STAGE;
#pragma unroll
        for (int s = 0; s < 2; s++) {
            uint32_t ah[2][4], al[2][4], bhr[8], blr[8];
            ldsm4(bhr,     base + O_WH + boff + s * 32);
            ldsm4(bhr + 4, base + O_WH + boff + 16 * 80 + s * 32);
            ldsm4(blr,     base + O_WL + boff + s * 32);
            ldsm4(blr + 4, base + O_WL + boff + 16 * 80 + s * 32);
#pragma unroll
            for (int mt = 0; mt < 2; mt++) {
                ldsm4(ah[mt], base + aoff + mt * 1280 + s * 32);
                ldsm4(al[mt], base + O_AL + aoff + mt * 1280 + s * 32);
            }
#pragma unroll
            for (int mt = 0; mt < 2; mt++)
#pragma unroll
                for (int nt = 0; nt < 4; nt++) {
                    mma16(acc[mt][nt], ah[mt], bhr + 2 * nt);
                    mma16(acc[mt][nt], al[mt], bhr + 2 * nt);
                    mma16(acc[mt][nt], ah[mt], blr + 2 * nt);
                }
        }
        if (more) {
            __syncthreads();
            STSS(1 - buf);
            __syncthreads();
        }
    }

    if (NORM) {
        __syncthreads();
        float ss0[2] = {0.f, 0.f}, ss1[2] = {0.f, 0.f};
#pragma unroll
        for (int mt = 0; mt < 2; mt++)
#pragma unroll
            for (int nt = 0; nt < 4; nt++) {
                ss0[mt] += acc[mt][nt][0] * acc[mt][nt][0] + acc[mt][nt][1] * acc[mt][nt][1];
                ss1[mt] += acc[mt][nt][2] * acc[mt][nt][2] + acc[mt][nt][3] * acc[mt][nt][3];
            }
#pragma unroll
        for (int mt = 0; mt < 2; mt++) {
            ss0[mt] += __shfl_xor_sync(0xffffffffu, ss0[mt], 1);
            ss0[mt] += __shfl_xor_sync(0xffffffffu, ss0[mt], 2);
            ss1[mt] += __shfl_xor_sync(0xffffffffu, ss1[mt], 1);
            ss1[mt] += __shfl_xor_sync(0xffffffffu, ss1[mt], 2);
            if (c == 0) {
                red[(wm * 32 + mt * 16 + g) * 2 + wn]     = ss0[mt];
                red[(wm * 32 + mt * 16 + g + 8) * 2 + wn] = ss1[mt];
            }
        }
        __syncthreads();
        float sc0[2], sc1[2];
#pragma unroll
        for (int mt = 0; mt < 2; mt++) {
            int r = (wm * 32 + mt * 16 + g) * 2;
            sc0[mt] = rsqrtf((red[r] + red[r + 1]) * (1.f / 64.f) + 1e-6f);
            r = (wm * 32 + mt * 16 + g + 8) * 2;
            sc1[mt] = rsqrtf((red[r] + red[r + 1]) * (1.f / 64.f) + 1e-6f);
        }
        float w0[4], w1[4];
#pragma unroll
        for (int nt = 0; nt < 4; nt++) {
            w0[nt] = nw[wn * 32 + nt * 8 + 2 * c];
            w1[nt] = nw[wn * 32 + nt * 8 + 2 * c + 1];
        }
#pragma unroll
        for (int mt = 0; mt < 2; mt++)
#pragma unroll
            for (int nt = 0; nt < 4; nt++) {
                acc[mt][nt][0] *= sc0[mt] * w0[nt];
                acc[mt][nt][1] *= sc0[mt] * w1[nt];
                acc[mt][nt][2] *= sc1[mt] * w0[nt];
                acc[mt][nt][3] *= sc1[mt] * w1[nt];
            }
    }

#pragma unroll
    for (int mt = 0; mt < 2; mt++)
#pragma unroll
        for (int nt = 0; nt < 4; nt++) {
            int r = m0 + wm * 32 + mt * 16 + g;
            int col = n0 + wn * 32 + nt * 8 + 2 * c;
            *(float2*)(C + (size_t)r * N + col) =
                make_float2(acc[mt][nt][0], acc[mt][nt][1]);
            *(float2*)(C + (size_t)(r + 8) * N + col) =
                make_float2(acc[mt][nt][2], acc[mt][nt][3]);
        }
}

// ======================================================================
// Attention (R7 body, passing). Epilogue writes AO as bf16 hi/lo.
// ======================================================================
__global__ void __launch_bounds__(256, 1) attn_mma(
    const float* __restrict__ Qg, const float* __restrict__ Kg,
    const float* __restrict__ Vg,
    uint32_t* __restrict__ AOh, uint32_t* __restrict__ AOl)
{
    extern __shared__ char smc[];
    constexpr int PW = 36;
    constexpr int TILE_W = 64 * PW;
    constexpr int BUFW = 4 * TILE_W;
    uint32_t* smw = (uint32_t*)smc;
    const uint32_t sbase = smem_u32(smc);

    const int tid = threadIdx.x;
    const int lane = tid & 31, w = tid >> 5;
    const int g = lane >> 2, c = lane & 3;
    const int r8 = lane & 7, mm = lane >> 3;
    const int b = blockIdx.z, hk = blockIdx.y, q0 = blockIdx.x * 32;
    const int head = hk * 4 + (w >> 1);
    const int qi = (w & 1) * 16;

    uint32_t qh[4][4], ql[4][4];
    {
        const float* r0 = Qg + (size_t)(b * SQ + q0 + qi + g) * HID + head * DH;
        const float* r1 = r0 + 8 * (size_t)HID;
#pragma unroll
        for (int s = 0; s < 4; s++) {
            const int cs = 16 * s + 2 * c;
            bfsplit2(r0[cs],     r0[cs + 1], qh[s][0], ql[s][0]);
            bfsplit2(r1[cs],     r1[cs + 1], qh[s][1], ql[s][1]);
            bfsplit2(r0[cs + 8], r0[cs + 9], qh[s][2], ql[s][2]);
            bfsplit2(r1[cs + 8], r1[cs + 9], qh[s][3], ql[s][3]);
        }
    }

    const int krow = tid >> 2;
    const int kcol = (tid & 3) * 16;
    const float* kbase = Kg + (size_t)b * SKV * (NHK * DH) + hk * DH + kcol;
    const float* vbase = Vg + (size_t)b * SKV * (NHK * DH) + hk * DH + kcol;

    float4 kr[4], vr[4];
    auto LDG = [&](int t) {
        const float* kp = kbase + (size_t)(t * 64 + krow) * (NHK * DH);
        const float* vp = vbase + (size_t)(t * 64 + krow) * (NHK * DH);
#pragma unroll
        for (int i = 0; i < 4; i++) {
            kr[i] = *(const float4*)(kp + i * 4);
            vr[i] = *(const float4*)(vp + i * 4);
        }
    };
    auto STS = [&](int buf) {
        uint32_t* KH = smw + buf * BUFW;
        uint32_t* KL = KH + TILE_W;
        uint32_t* VH = KH + 2 * TILE_W;
        uint32_t* VL = KH + 3 * TILE_W;
        const int wb = krow * PW + (kcol >> 1);
#pragma unroll
        for (int i = 0; i < 4; i++) {
            uint32_t h0, l0, h1, l1;
            bfsplit2(kr[i].x, kr[i].y, h0, l0);
            bfsplit2(kr[i].z, kr[i].w, h1, l1);
            KH[wb + 2 * i] = h0; KH[wb + 2 * i + 1] = h1;
            KL[wb + 2 * i] = l0; KL[wb + 2 * i + 1] = l1;
            bfsplit2(vr[i].x, vr[i].y, h0, l0);
            bfsplit2(vr[i].z, vr[i].w, h1, l1);
            VH[wb + 2 * i] = h0; VH[wb + 2 * i + 1] = h1;
            VL[wb + 2 * i] = l0; VL[wb + 2 * i + 1] = l1;
        }
    };

    float oacc[8][4];
#pragma unroll
    for (int j = 0; j < 8; j++)
#pragma unroll
        for (int i = 0; i < 4; i++) oacc[j][i] = 0.f;
    float lsum0 = 0.f, lsum1 = 0.f;

    const uint32_t k_off = (uint32_t)r8 * 144u + (uint32_t)mm * 16u;
    const uint32_t v_off = ((uint32_t)(8 * (mm & 1) + r8)) * 144u + (uint32_t)(mm >> 1) * 16u;

    LDG(0); STS(0);
    __syncthreads();

    for (int t = 0; t < SKV / 64; t++) {
        const int cur = t & 1;
        if (t < SKV / 64 - 1) LDG(t + 1);
        const uint32_t kh_b = sbase + (uint32_t)(cur * BUFW) * 4u;
        const uint32_t kl_b = kh_b + TILE_W * 4u;
        const uint32_t vh_b = kh_b + 2u * TILE_W * 4u;
        const uint32_t vl_b = kh_b + 3u * TILE_W * 4u;

        float sacc[8][4];
#pragma unroll
        for (int j = 0; j < 8; j++) {
            const uint32_t ro = (uint32_t)(8 * j) * 144u;
            uint32_t kh[8], kl[8];
            ldsm4(kh,     kh_b + ro + k_off);
            ldsm4(kh + 4, kh_b + ro + k_off + 64u);
            ldsm4(kl,     kl_b + ro + k_off);
            ldsm4(kl + 4, kl_b + ro + k_off + 64u);
#pragma unroll
            for (int i = 0; i < 4; i++) sacc[j][i] = 0.f;
#pragma unroll
            for (int s = 0; s < 4; s++) {
                mma16(sacc[j], qh[s], kh + 2 * s);
                mma16(sacc[j], ql[s], kh + 2 * s);
                mma16(sacc[j], qh[s], kl + 2 * s);
            }
        }

        uint32_t pah[4][4], pal[4][4];
        float rs0 = 0.f, rs1 = 0.f;
#pragma unroll
        for (int j = 0; j < 8; j++) {
            float p0 = __expf(sacc[j][0]);
            float p1 = __expf(sacc[j][1]);
            float p2 = __expf(sacc[j][2]);
            float p3 = __expf(sacc[j][3]);
            rs0 += p0 + p1;
            rs1 += p2 + p3;
            const int s = j >> 1, o = (j & 1) * 2;
            bfsplit2(p0, p1, pah[s][o],     pal[s][o]);
            bfsplit2(p2, p3, pah[s][o + 1], pal[s][o + 1]);
        }
        rs0 += __shfl_xor_sync(0xffffffffu, rs0, 1);
        rs0 += __shfl_xor_sync(0xffffffffu, rs0, 2);
        rs1 += __shfl_xor_sync(0xffffffffu, rs1, 1);
        rs1 += __shfl_xor_sync(0xffffffffu, rs1, 2);
        lsum0 += rs0;
        lsum1 += rs1;

#pragma unroll
        for (int s = 0; s < 4; s++) {
            const uint32_t so = (uint32_t)(16 * s) * 144u;
#pragma unroll
            for (int jj = 0; jj < 4; jj++) {
                const uint32_t co = so + (uint32_t)(32 * jj) + v_off;
                uint32_t vh[4], vl[4];
                ldsm4t(vh, vh_b + co);
                ldsm4t(vl, vl_b + co);
                mma16(oacc[2 * jj],     pah[s], vh);
                mma16(oacc[2 * jj],     pal[s], vh);
                mma16(oacc[2 * jj],     pah[s], vl);
                mma16(oacc[2 * jj + 1], pah[s], vh + 2);
                mma16(oacc[2 * jj + 1], pal[s], vh + 2);
                mma16(oacc[2 * jj + 1], pah[s], vl + 2);
            }
        }

        if (t < SKV / 64 - 1) {
            __syncthreads();
            STS(1 - cur);
            __syncthreads();
        }
    }

    // --- epilogue: normalize, write bf16 hi/lo split AO ---
    const float i0 = 1.f / lsum0, i1 = 1.f / lsum1;
    const int row0 = b * SQ + q0 + qi + g;
    const int colw = head * 32 + c;
#pragma unroll
    for (int j = 0; j < 8; j++) {
        uint32_t h0, l0, h1, l1;
        bfsplit2(oacc[j][0] * i0, oacc[j][1] * i0, h0, l0);
        bfsplit2(oacc[j][2] * i1, oacc[j][3] * i1, h1, l1);
        const int idx0 = row0 * 512 + colw + j * 4;
        const int idx1 = idx0 + 8 * 512;
        AOh[idx0] = h0; AOl[idx0] = l0;
        AOh[idx1] = h1; AOl[idx1] = l1;
    }
}

// ======================================================================
extern "C" void kernel_launch(void* const* d_in, const int* in_sizes, int n_in,
                              void* d_out, int out_size)
{
    (void)in_sizes; (void)n_in; (void)out_size;
    const float* inputs = (const float*)d_in[0];
    const float* latent = (const float*)d_in[1];
    const float* wq     = (const float*)d_in[2];
    const float* wk     = (const float*)d_in[3];
    const float* wv     = (const float*)d_in[4];
    const float* wo     = (const float*)d_in[5];
    const float* qnw    = (const float*)d_in[6];
    const float* knw    = (const float*)d_in[7];
    float* out = (float*)d_out;

    float *Qb, *Kb, *Vb;
    cudaGetSymbolAddress((void**)&Qb, g_Q);
    cudaGetSymbolAddress((void**)&Kb, g_K);
    cudaGetSymbolAddress((void**)&Vb, g_V);
    uint4 *inh, *inl, *lath, *latl, *wqh, *wql, *wkh, *wkl, *wvh, *wvl, *woh, *wol;
    cudaGetSymbolAddress((void**)&inh,  g_inh);  cudaGetSymbolAddress((void**)&inl,  g_inl);
    cudaGetSymbolAddress((void**)&lath, g_lath); cudaGetSymbolAddress((void**)&latl, g_latl);
    cudaGetSymbolAddress((void**)&wqh,  g_wqh);  cudaGetSymbolAddress((void**)&wql,  g_wql);
    cudaGetSymbolAddress((void**)&wkh,  g_wkh);  cudaGetSymbolAddress((void**)&wkl,  g_wkl);
    cudaGetSymbolAddress((void**)&wvh,  g_wvh);  cudaGetSymbolAddress((void**)&wvl,  g_wvl);
    cudaGetSymbolAddress((void**)&woh,  g_woh);  cudaGetSymbolAddress((void**)&wol,  g_wol);
    uint4 *aoh4, *aol4;
    cudaGetSymbolAddress((void**)&aoh4, g_AOh);  cudaGetSymbolAddress((void**)&aol4, g_AOl);

    const int SMG = 2 * 30720 + 1024;   // 62464
    const int SMA = 2 * 4 * 2304 * 4;   // 73728
    cudaFuncSetAttribute(gemm_bf3<true>,  cudaFuncAttributeMaxDynamicSharedMemorySize, SMG);
    cudaFuncSetAttribute(gemm_bf3<false>, cudaFuncAttributeMaxDynamicSharedMemorySize, SMG);
    cudaFuncSetAttribute(attn_mma, cudaFuncAttributeMaxDynamicSharedMemorySize, SMA);

    // ---- pre-split all GEMM operands to bf16 hi/lo ----
    auto split = [&](const float* x, uint4* h, uint4* l, int n) {
        int n8 = n / 8;
        presplit<<<(n8 + 255) / 256, 256>>>((const float4*)x, h, l, n8);
    };
    split(inputs, inh,  inl,  8192 * 1024);
    split(latent, lath, latl, 1024 * 1024);
    split(wq,     wqh,  wql,  1024 * 1024);
    split(wk,     wkh,  wkl,   256 * 1024);
    split(wv,     wvh,  wvl,   256 * 1024);
    split(wo,     woh,  wol,  1024 * 1024);

    dim3 blk(256);
    // Q = rmsnorm(latent @ wq^T)   [1024 x 1024]
    gemm_bf3<true ><<<dim3(16, 8), blk, SMG>>>((const uint16_t*)lath, (const uint16_t*)latl,
        (const uint16_t*)wqh, (const uint16_t*)wql, qnw, Qb, BATCH * SQ, NH * DH, HID);
    // K = rmsnorm(inputs @ wk^T)   [8192 x 256]
    gemm_bf3<true ><<<dim3(4, 64), blk, SMG>>>((const uint16_t*)inh, (const uint16_t*)inl,
        (const uint16_t*)wkh, (const uint16_t*)wkl, knw, Kb, BATCH * SKV, NHK * DH, HID);
    // V = inputs @ wv^T            [8192 x 256]
    gemm_bf3<false><<<dim3(4, 64), blk, SMG>>>((const uint16_t*)inh, (const uint16_t*)inl,
        (const uint16_t*)wvh, (const uint16_t*)wvl, nullptr, Vb, BATCH * SKV, NHK * DH, HID);
    // attention -> split bf16 AO
    attn_mma<<<dim3(SQ / 32, NHK, BATCH), blk, SMA>>>(Qb, Kb, Vb,
        (uint32_t*)aoh4, (uint32_t*)aol4);
    // out = AO @ wo^T              [1024 x 1024]
    gemm_bf3<false><<<dim3(16, 8), blk, SMG>>>((const uint16_t*)aoh4, (const uint16_t*)aol4,
        (const uint16_t*)woh, (const uint16_t*)wol, nullptr, out, BATCH * SQ, HID, HID);
}

// round 12
// speedup vs baseline: 1.5723x; 1.0198x over previous
#include <cuda_runtime.h>
#include <cstdint>

#define HID   1024
#define BATCH 2
#define SKV   4096
#define SQ    512
#define NH    16
#define NHK   4
#define DH    64

// ---------------- scratch (all GEMM-consumed buffers uint4 => 16B aligned) ----------------
__device__ float g_Q [BATCH * SQ * NH * DH];
__device__ uint4 g_inh [8192 * 1024 / 8], g_inl [8192 * 1024 / 8];
__device__ uint4 g_lath[1024 * 1024 / 8], g_latl[1024 * 1024 / 8];
__device__ uint4 g_wqh [1024 * 1024 / 8], g_wql [1024 * 1024 / 8];
__device__ uint4 g_wkh [ 256 * 1024 / 8], g_wkl [ 256 * 1024 / 8];
__device__ uint4 g_wvh [ 256 * 1024 / 8], g_wvl [ 256 * 1024 / 8];
__device__ uint4 g_woh [1024 * 1024 / 8], g_wol [1024 * 1024 / 8];
// K/V in bf16 hi/lo, written by projection GEMM epilogues
__device__ uint4 g_Kh[8192 * 256 / 8], g_Kl[8192 * 256 / 8];
__device__ uint4 g_Vh[8192 * 256 / 8], g_Vl[8192 * 256 / 8];
// attention output, bf16 hi/lo
__device__ uint4 g_AOh[1024 * 512 / 4], g_AOl[1024 * 512 / 4];

// ---------------- helpers ----------------
__device__ __forceinline__ uint32_t pack_bf(float x, float y) {
    uint32_t r;
    asm("cvt.rn.bf16x2.f32 %0, %1, %2;" : "=r"(r) : "f"(y), "f"(x));
    return r;
}
__device__ __forceinline__ void bfsplit2(float x, float y, uint32_t& h, uint32_t& l) {
    h = pack_bf(x, y);
    float hx = __uint_as_float(h << 16);
    float hy = __uint_as_float(h & 0xffff0000u);
    l = pack_bf(x - hx, y - hy);
}
__device__ __forceinline__ void mma16(float* d, const uint32_t* a, const uint32_t* b) {
    asm volatile(
        "mma.sync.aligned.m16n8k16.row.col.f32.bf16.bf16.f32 "
        "{%0,%1,%2,%3},{%4,%5,%6,%7},{%8,%9},{%0,%1,%2,%3};"
        : "+f"(d[0]), "+f"(d[1]), "+f"(d[2]), "+f"(d[3])
        : "r"(a[0]), "r"(a[1]), "r"(a[2]), "r"(a[3]), "r"(b[0]), "r"(b[1]));
}
__device__ __forceinline__ uint32_t smem_u32(const void* p) {
    uint32_t a;
    asm("{ .reg .u64 t; cvta.to.shared.u64 t, %1; cvt.u32.u64 %0, t; }" : "=r"(a) : "l"(p));
    return a;
}
__device__ __forceinline__ void ldsm4(uint32_t* r, uint32_t addr) {
    asm volatile("ldmatrix.sync.aligned.m8n8.x4.shared.b16 {%0,%1,%2,%3}, [%4];"
        : "=r"(r[0]), "=r"(r[1]), "=r"(r[2]), "=r"(r[3]) : "r"(addr));
}
__device__ __forceinline__ void ldsm4t(uint32_t* r, uint32_t addr) {
    asm volatile("ldmatrix.sync.aligned.m8n8.x4.trans.shared.b16 {%0,%1,%2,%3}, [%4];"
        : "=r"(r[0]), "=r"(r[1]), "=r"(r[2]), "=r"(r[3]) : "r"(addr));
}

// ======================================================================
// presplit: X (f32) -> Xh, Xl (bf16 halfs, same layout)
// ======================================================================
__global__ void presplit(const float4* __restrict__ x,
                         uint4* __restrict__ h, uint4* __restrict__ l, int n8)
{
    int i = blockIdx.x * blockDim.x + threadIdx.x;
    if (i >= n8) return;
    float4 v0 = x[2 * i], v1 = x[2 * i + 1];
    uint4 H, L;
    bfsplit2(v0.x, v0.y, H.x, L.x);
    bfsplit2(v0.z, v0.w, H.y, L.y);
    bfsplit2(v1.x, v1.y, H.z, L.z);
    bfsplit2(v1.z, v1.w, H.w, L.w);
    h[i] = H; l[i] = L;
}

// ======================================================================
// gemm_bf3: C[M,N] = A[M,K] @ W[N,K]^T, 3-term double-bf16.
// Pre-split bf16 operands, register-prefetch LDG(uint4) -> STS double
// buffering (R10-proven mechanics), ldmatrix fragment loads.
// SPLITOUT: write bf16 hi/lo (Ch/Cl) instead of f32 C.
// BM=128, BN=64, BK=32, 8 warps, row pitch 80B.
// ======================================================================
template <bool NORM, bool SPLITOUT>
__global__ void __launch_bounds__(256, 2) gemm_bf3(
    const uint16_t* __restrict__ Ah, const uint16_t* __restrict__ Al,
    const uint16_t* __restrict__ Wh, const uint16_t* __restrict__ Wl,
    const float* __restrict__ nw, float* __restrict__ C,
    uint32_t* __restrict__ Ch, uint32_t* __restrict__ Cl,
    int M, int N, int Kdim)
{
    extern __shared__ char smc[];
    const uint32_t sb = smem_u32(smc);
    constexpr int STAGE = 30720;         // Ah(10240)+Al(10240)+Wh(5120)+Wl(5120)
    constexpr int O_AL = 10240, O_WH = 20480, O_WL = 25600;
    float* red = (float*)(smc + 2 * STAGE);

    const int tid = threadIdx.x, lane = tid & 31, wid = tid >> 5;
    const int wm = wid >> 1, wn = wid & 1;
    const int g = lane >> 2, c = lane & 3;
    const int m0 = blockIdx.y * 128, n0 = blockIdx.x * 64;

    float acc[2][4][4];
#pragma unroll
    for (int mt = 0; mt < 2; mt++)
#pragma unroll
        for (int nt = 0; nt < 4; nt++)
#pragma unroll
            for (int i = 0; i < 4; i++) acc[mt][nt][i] = 0.f;

    // staging: row = tid>>2 (0..63), chunk = tid&3 (16B each)
    const int srow = tid >> 2, sch = tid & 3;
    const size_t abase0 = (size_t)(m0 + srow) * Kdim + sch * 8;
    const size_t abase1 = (size_t)(m0 + srow + 64) * Kdim + sch * 8;
    const size_t wbase  = (size_t)(n0 + srow) * Kdim + sch * 8;
    const int ro = srow * 80 + sch * 16;

    uint4 rAh0, rAh1, rAl0, rAl1, rWh, rWl;
    auto LDGS = [&](int kt) {
        rAh0 = *(const uint4*)(Ah + abase0 + kt);
        rAh1 = *(const uint4*)(Ah + abase1 + kt);
        rAl0 = *(const uint4*)(Al + abase0 + kt);
        rAl1 = *(const uint4*)(Al + abase1 + kt);
        rWh  = *(const uint4*)(Wh + wbase + kt);
        rWl  = *(const uint4*)(Wl + wbase + kt);
    };
    auto STSS = [&](int buf) {
        char* d = smc + buf * STAGE;
        *(uint4*)(d + ro)                  = rAh0;
        *(uint4*)(d + 64 * 80 + ro)        = rAh1;
        *(uint4*)(d + O_AL + ro)           = rAl0;
        *(uint4*)(d + O_AL + 64 * 80 + ro) = rAl1;
        *(uint4*)(d + O_WH + ro)           = rWh;
        *(uint4*)(d + O_WL + ro)           = rWl;
    };

    const uint32_t aoff = (uint32_t)((wm * 32 + (lane & 7) + ((lane >> 3) & 1) * 8) * 80
                                     + ((lane >> 4) & 1) * 16);
    const uint32_t boff = (uint32_t)((wn * 32 + (lane & 7) + ((lane >> 4) & 1) * 8) * 80
                                     + ((lane >> 3) & 1) * 16);

    LDGS(0); STSS(0);
    __syncthreads();

    for (int kt = 0; kt < Kdim; kt += 32) {
        const int buf = (kt >> 5) & 1;
        const bool more = (kt + 32 < Kdim);
        if (more) LDGS(kt + 32);

        const uint32_t base = sb + buf * STAGE;
#pragma unroll
        for (int s = 0; s < 2; s++) {
            uint32_t ah[2][4], al[2][4], bhr[8], blr[8];
            ldsm4(bhr,     base + O_WH + boff + s * 32);
            ldsm4(bhr + 4, base + O_WH + boff + 16 * 80 + s * 32);
            ldsm4(blr,     base + O_WL + boff + s * 32);
            ldsm4(blr + 4, base + O_WL + boff + 16 * 80 + s * 32);
#pragma unroll
            for (int mt = 0; mt < 2; mt++) {
                ldsm4(ah[mt], base + aoff + mt * 1280 + s * 32);
                ldsm4(al[mt], base + O_AL + aoff + mt * 1280 + s * 32);
            }
#pragma unroll
            for (int mt = 0; mt < 2; mt++)
#pragma unroll
                for (int nt = 0; nt < 4; nt++) {
                    mma16(acc[mt][nt], ah[mt], bhr + 2 * nt);
                    mma16(acc[mt][nt], al[mt], bhr + 2 * nt);
                    mma16(acc[mt][nt], ah[mt], blr + 2 * nt);
                }
        }
        if (more) {
            __syncthreads();
            STSS(1 - buf);
            __syncthreads();
        }
    }

    if (NORM) {
        __syncthreads();
        float ss0[2] = {0.f, 0.f}, ss1[2] = {0.f, 0.f};
#pragma unroll
        for (int mt = 0; mt < 2; mt++)
#pragma unroll
            for (int nt = 0; nt < 4; nt++) {
                ss0[mt] += acc[mt][nt][0] * acc[mt][nt][0] + acc[mt][nt][1] * acc[mt][nt][1];
                ss1[mt] += acc[mt][nt][2] * acc[mt][nt][2] + acc[mt][nt][3] * acc[mt][nt][3];
            }
#pragma unroll
        for (int mt = 0; mt < 2; mt++) {
            ss0[mt] += __shfl_xor_sync(0xffffffffu, ss0[mt], 1);
            ss0[mt] += __shfl_xor_sync(0xffffffffu, ss0[mt], 2);
            ss1[mt] += __shfl_xor_sync(0xffffffffu, ss1[mt], 1);
            ss1[mt] += __shfl_xor_sync(0xffffffffu, ss1[mt], 2);
            if (c == 0) {
                red[(wm * 32 + mt * 16 + g) * 2 + wn]     = ss0[mt];
                red[(wm * 32 + mt * 16 + g + 8) * 2 + wn] = ss1[mt];
            }
        }
        __syncthreads();
        float sc0[2], sc1[2];
#pragma unroll
        for (int mt = 0; mt < 2; mt++) {
            int r = (wm * 32 + mt * 16 + g) * 2;
            sc0[mt] = rsqrtf((red[r] + red[r + 1]) * (1.f / 64.f) + 1e-6f);
            r = (wm * 32 + mt * 16 + g + 8) * 2;
            sc1[mt] = rsqrtf((red[r] + red[r + 1]) * (1.f / 64.f) + 1e-6f);
        }
        float w0[4], w1[4];
#pragma unroll
        for (int nt = 0; nt < 4; nt++) {
            w0[nt] = nw[wn * 32 + nt * 8 + 2 * c];
            w1[nt] = nw[wn * 32 + nt * 8 + 2 * c + 1];
        }
#pragma unroll
        for (int mt = 0; mt < 2; mt++)
#pragma unroll
            for (int nt = 0; nt < 4; nt++) {
                acc[mt][nt][0] *= sc0[mt] * w0[nt];
                acc[mt][nt][1] *= sc0[mt] * w1[nt];
                acc[mt][nt][2] *= sc1[mt] * w0[nt];
                acc[mt][nt][3] *= sc1[mt] * w1[nt];
            }
    }

#pragma unroll
    for (int mt = 0; mt < 2; mt++)
#pragma unroll
        for (int nt = 0; nt < 4; nt++) {
            const int r = m0 + wm * 32 + mt * 16 + g;
            const int col = n0 + wn * 32 + nt * 8 + 2 * c;
            if (SPLITOUT) {
                uint32_t h0, l0, h1, l1;
                bfsplit2(acc[mt][nt][0], acc[mt][nt][1], h0, l0);
                bfsplit2(acc[mt][nt][2], acc[mt][nt][3], h1, l1);
                const int i0 = r * (N >> 1) + (col >> 1);
                const int i1 = (r + 8) * (N >> 1) + (col >> 1);
                Ch[i0] = h0; Cl[i0] = l0;
                Ch[i1] = h1; Cl[i1] = l1;
            } else {
                *(float2*)(C + (size_t)r * N + col) =
                    make_float2(acc[mt][nt][0], acc[mt][nt][1]);
                *(float2*)(C + (size_t)(r + 8) * N + col) =
                    make_float2(acc[mt][nt][2], acc[mt][nt][3]);
            }
        }
}

// ======================================================================
// Attention. K/V arrive pre-split (bf16 hi/lo); mainloop stages them via
// LDG(uint4) register prefetch + STS (no split ALU). Compute body and
// epilogue identical to R10 (passing).
// ======================================================================
__global__ void __launch_bounds__(256, 1) attn_mma(
    const float* __restrict__ Qg,
    const uint16_t* __restrict__ Khg, const uint16_t* __restrict__ Klg,
    const uint16_t* __restrict__ Vhg, const uint16_t* __restrict__ Vlg,
    uint32_t* __restrict__ AOh, uint32_t* __restrict__ AOl)
{
    extern __shared__ char smc[];
    constexpr int TILE_B = 9216;         // 64 rows x 144B pitch
    constexpr int BUF_B  = 4 * TILE_B;   // KH,KL,VH,VL
    const uint32_t sbase = smem_u32(smc);

    const int tid = threadIdx.x;
    const int lane = tid & 31, w = tid >> 5;
    const int g = lane >> 2, c = lane & 3;
    const int r8 = lane & 7, mm = lane >> 3;
    const int b = blockIdx.z, hk = blockIdx.y, q0 = blockIdx.x * 32;
    const int head = hk * 4 + (w >> 1);
    const int qi = (w & 1) * 16;

    // ---- Q fragments: double-bf16 hi/lo ----
    uint32_t qh[4][4], ql[4][4];
    {
        const float* r0 = Qg + (size_t)(b * SQ + q0 + qi + g) * HID + head * DH;
        const float* r1 = r0 + 8 * (size_t)HID;
#pragma unroll
        for (int s = 0; s < 4; s++) {
            const int cs = 16 * s + 2 * c;
            bfsplit2(r0[cs],     r0[cs + 1], qh[s][0], ql[s][0]);
            bfsplit2(r1[cs],     r1[cs + 1], qh[s][1], ql[s][1]);
            bfsplit2(r0[cs + 8], r0[cs + 9], qh[s][2], ql[s][2]);
            bfsplit2(r1[cs + 8], r1[cs + 9], qh[s][3], ql[s][3]);
        }
    }

    // staging: row crow (0..63), two 16B chunks per matrix
    const int crow = tid >> 2;
    const int cch2 = (tid & 3) * 2;
    uint4 rKH[2], rKL[2], rVH[2], rVL[2];
    auto LDGA = [&](int t) {
        const size_t srow = (size_t)(b * SKV + t * 64 + crow) * 256 + hk * 64;
#pragma unroll
        for (int u = 0; u < 2; u++) {
            const size_t soff = srow + (size_t)(cch2 + u) * 8;
            rKH[u] = *(const uint4*)(Khg + soff);
            rKL[u] = *(const uint4*)(Klg + soff);
            rVH[u] = *(const uint4*)(Vhg + soff);
            rVL[u] = *(const uint4*)(Vlg + soff);
        }
    };
    auto STSA = [&](int buf) {
        char* d = smc + buf * BUF_B;
#pragma unroll
        for (int u = 0; u < 2; u++) {
            const int doff = crow * 144 + (cch2 + u) * 16;
            *(uint4*)(d + doff)              = rKH[u];
            *(uint4*)(d + TILE_B + doff)     = rKL[u];
            *(uint4*)(d + 2 * TILE_B + doff) = rVH[u];
            *(uint4*)(d + 3 * TILE_B + doff) = rVL[u];
        }
    };

    float oacc[8][4];
#pragma unroll
    for (int j = 0; j < 8; j++)
#pragma unroll
        for (int i = 0; i < 4; i++) oacc[j][i] = 0.f;
    float lsum0 = 0.f, lsum1 = 0.f;

    const uint32_t k_off = (uint32_t)r8 * 144u + (uint32_t)mm * 16u;
    const uint32_t v_off = ((uint32_t)(8 * (mm & 1) + r8)) * 144u + (uint32_t)(mm >> 1) * 16u;

    LDGA(0); STSA(0);
    __syncthreads();

    for (int t = 0; t < SKV / 64; t++) {
        const int cur = t & 1;
        if (t < SKV / 64 - 1) LDGA(t + 1);

        const uint32_t kh_b = sbase + (uint32_t)cur * BUF_B;
        const uint32_t kl_b = kh_b + TILE_B;
        const uint32_t vh_b = kh_b + 2 * TILE_B;
        const uint32_t vl_b = kh_b + 3 * TILE_B;

        // --- S = Q @ K^T (3-term double-bf16) ---
        float sacc[8][4];
#pragma unroll
        for (int j = 0; j < 8; j++) {
            const uint32_t ro = (uint32_t)(8 * j) * 144u;
            uint32_t kh[8], kl[8];
            ldsm4(kh,     kh_b + ro + k_off);
            ldsm4(kh + 4, kh_b + ro + k_off + 64u);
            ldsm4(kl,     kl_b + ro + k_off);
            ldsm4(kl + 4, kl_b + ro + k_off + 64u);
#pragma unroll
            for (int i = 0; i < 4; i++) sacc[j][i] = 0.f;
#pragma unroll
            for (int s = 0; s < 4; s++) {
                mma16(sacc[j], qh[s], kh + 2 * s);
                mma16(sacc[j], ql[s], kh + 2 * s);
                mma16(sacc[j], qh[s], kl + 2 * s);
            }
        }

        // --- P = exp(S): fp32 row-sum, bf16 hi/lo A-frags in regs ---
        uint32_t pah[4][4], pal[4][4];
        float rs0 = 0.f, rs1 = 0.f;
#pragma unroll
        for (int j = 0; j < 8; j++) {
            float p0 = __expf(sacc[j][0]);
            float p1 = __expf(sacc[j][1]);
            float p2 = __expf(sacc[j][2]);
            float p3 = __expf(sacc[j][3]);
            rs0 += p0 + p1;
            rs1 += p2 + p3;
            const int s = j >> 1, o = (j & 1) * 2;
            bfsplit2(p0, p1, pah[s][o],     pal[s][o]);
            bfsplit2(p2, p3, pah[s][o + 1], pal[s][o + 1]);
        }
        rs0 += __shfl_xor_sync(0xffffffffu, rs0, 1);
        rs0 += __shfl_xor_sync(0xffffffffu, rs0, 2);
        rs1 += __shfl_xor_sync(0xffffffffu, rs1, 1);
        rs1 += __shfl_xor_sync(0xffffffffu, rs1, 2);
        lsum0 += rs0;
        lsum1 += rs1;

        // --- O += P @ V (3-term double-bf16, V via ldmatrix.trans) ---
#pragma unroll
        for (int s = 0; s < 4; s++) {
            const uint32_t so = (uint32_t)(16 * s) * 144u;
#pragma unroll
            for (int jj = 0; jj < 4; jj++) {
                const uint32_t co = so + (uint32_t)(32 * jj) + v_off;
                uint32_t vh[4], vl[4];
                ldsm4t(vh, vh_b + co);
                ldsm4t(vl, vl_b + co);
                mma16(oacc[2 * jj],     pah[s], vh);
                mma16(oacc[2 * jj],     pal[s], vh);
                mma16(oacc[2 * jj],     pah[s], vl);
                mma16(oacc[2 * jj + 1], pah[s], vh + 2);
                mma16(oacc[2 * jj + 1], pal[s], vh + 2);
                mma16(oacc[2 * jj + 1], pah[s], vl + 2);
            }
        }

        if (t < SKV / 64 - 1) {
            __syncthreads();
            STSA(1 - cur);
            __syncthreads();
        }
    }

    // --- epilogue: normalize, write bf16 hi/lo split AO ---
    const float i0 = 1.f / lsum0, i1 = 1.f / lsum1;
    const int row0 = b * SQ + q0 + qi + g;
    const int colw = head * 32 + c;
#pragma unroll
    for (int j = 0; j < 8; j++) {
        uint32_t h0, l0, h1, l1;
        bfsplit2(oacc[j][0] * i0, oacc[j][1] * i0, h0, l0);
        bfsplit2(oacc[j][2] * i1, oacc[j][3] * i1, h1, l1);
        const int idx0 = row0 * 512 + colw + j * 4;
        const int idx1 = idx0 + 8 * 512;
        AOh[idx0] = h0; AOl[idx0] = l0;
        AOh[idx1] = h1; AOl[idx1] = l1;
    }
}

// ======================================================================
extern "C" void kernel_launch(void* const* d_in, const int* in_sizes, int n_in,
                              void* d_out, int out_size)
{
    (void)in_sizes; (void)n_in; (void)out_size;
    const float* inputs = (const float*)d_in[0];
    const float* latent = (const float*)d_in[1];
    const float* wq     = (const float*)d_in[2];
    const float* wk     = (const float*)d_in[3];
    const float* wv     = (const float*)d_in[4];
    const float* wo     = (const float*)d_in[5];
    const float* qnw    = (const float*)d_in[6];
    const float* knw    = (const float*)d_in[7];
    float* out = (float*)d_out;

    float* Qb;
    cudaGetSymbolAddress((void**)&Qb, g_Q);
    uint4 *inh, *inl, *lath, *latl, *wqh, *wql, *wkh, *wkl, *wvh, *wvl, *woh, *wol;
    cudaGetSymbolAddress((void**)&inh,  g_inh);  cudaGetSymbolAddress((void**)&inl,  g_inl);
    cudaGetSymbolAddress((void**)&lath, g_lath); cudaGetSymbolAddress((void**)&latl, g_latl);
    cudaGetSymbolAddress((void**)&wqh,  g_wqh);  cudaGetSymbolAddress((void**)&wql,  g_wql);
    cudaGetSymbolAddress((void**)&wkh,  g_wkh);  cudaGetSymbolAddress((void**)&wkl,  g_wkl);
    cudaGetSymbolAddress((void**)&wvh,  g_wvh);  cudaGetSymbolAddress((void**)&wvl,  g_wvl);
    cudaGetSymbolAddress((void**)&woh,  g_woh);  cudaGetSymbolAddress((void**)&wol,  g_wol);
    uint4 *kh4, *kl4, *vh4, *vl4, *aoh4, *aol4;
    cudaGetSymbolAddress((void**)&kh4, g_Kh);    cudaGetSymbolAddress((void**)&kl4, g_Kl);
    cudaGetSymbolAddress((void**)&vh4, g_Vh);    cudaGetSymbolAddress((void**)&vl4, g_Vl);
    cudaGetSymbolAddress((void**)&aoh4, g_AOh);  cudaGetSymbolAddress((void**)&aol4, g_AOl);

    const int SMG = 2 * 30720 + 1024;   // 62464
    const int SMA = 2 * 4 * 9216;       // 73728
    cudaFuncSetAttribute(gemm_bf3<true,  false>, cudaFuncAttributeMaxDynamicSharedMemorySize, SMG);
    cudaFuncSetAttribute(gemm_bf3<true,  true >, cudaFuncAttributeMaxDynamicSharedMemorySize, SMG);
    cudaFuncSetAttribute(gemm_bf3<false, true >, cudaFuncAttributeMaxDynamicSharedMemorySize, SMG);
    cudaFuncSetAttribute(gemm_bf3<false, false>, cudaFuncAttributeMaxDynamicSharedMemorySize, SMG);
    cudaFuncSetAttribute(attn_mma, cudaFuncAttributeMaxDynamicSharedMemorySize, SMA);

    // ---- pre-split all GEMM operands to bf16 hi/lo ----
    auto split = [&](const float* x, uint4* h, uint4* l, int n) {
        int n8 = n / 8;
        presplit<<<(n8 + 255) / 256, 256>>>((const float4*)x, h, l, n8);
    };
    split(inputs, inh,  inl,  8192 * 1024);
    split(latent, lath, latl, 1024 * 1024);
    split(wq,     wqh,  wql,  1024 * 1024);
    split(wk,     wkh,  wkl,   256 * 1024);
    split(wv,     wvh,  wvl,   256 * 1024);
    split(wo,     woh,  wol,  1024 * 1024);

    dim3 blk(256);
    // Q = rmsnorm(latent @ wq^T) -> f32          [1024 x 1024]
    gemm_bf3<true, false><<<dim3(16, 8), blk, SMG>>>(
        (const uint16_t*)lath, (const uint16_t*)latl,
        (const uint16_t*)wqh, (const uint16_t*)wql,
        qnw, Qb, nullptr, nullptr, BATCH * SQ, NH * DH, HID);
    // K = rmsnorm(inputs @ wk^T) -> bf16 hi/lo   [8192 x 256]
    gemm_bf3<true, true><<<dim3(4, 64), blk, SMG>>>(
        (const uint16_t*)inh, (const uint16_t*)inl,
        (const uint16_t*)wkh, (const uint16_t*)wkl,
        knw, nullptr, (uint32_t*)kh4, (uint32_t*)kl4, BATCH * SKV, NHK * DH, HID);
    // V = inputs @ wv^T -> bf16 hi/lo            [8192 x 256]
    gemm_bf3<false, true><<<dim3(4, 64), blk, SMG>>>(
        (const uint16_t*)inh, (const uint16_t*)inl,
        (const uint16_t*)wvh, (const uint16_t*)wvl,
        nullptr, nullptr, (uint32_t*)vh4, (uint32_t*)vl4, BATCH * SKV, NHK * DH, HID);
    // attention -> bf16 hi/lo AO
    attn_mma<<<dim3(SQ / 32, NHK, BATCH), blk, SMA>>>(
        Qb, (const uint16_t*)kh4, (const uint16_t*)kl4,
        (const uint16_t*)vh4, (const uint16_t*)vl4,
        (uint32_t*)aoh4, (uint32_t*)aol4);
    // out = AO @ wo^T -> f32                     [1024 x 1024]
    gemm_bf3<false, false><<<dim3(16, 8), blk, SMG>>>(
        (const uint16_t*)aoh4, (const uint16_t*)aol4,
        (const uint16_t*)woh, (const uint16_t*)wol,
        nullptr, out, nullptr, nullptr, BATCH * SQ, HID, HID);
}

// round 13
// speedup vs baseline: 1.6225x; 1.0319x over previous
#include <cuda_runtime.h>
#include <cstdint>

#define HID   1024
#define BATCH 2
#define SKV   4096
#define SQ    512
#define NH    16
#define NHK   4
#define DH    64

// ---------------- scratch (all GEMM-consumed buffers uint4 => 16B aligned) ----------------
__device__ float g_Q [BATCH * SQ * NH * DH];
__device__ uint4 g_inh [8192 * 1024 / 8], g_inl [8192 * 1024 / 8];
__device__ uint4 g_lath[1024 * 1024 / 8], g_latl[1024 * 1024 / 8];
__device__ uint4 g_wqh [1024 * 1024 / 8], g_wql [1024 * 1024 / 8];
__device__ uint4 g_wkh [ 256 * 1024 / 8], g_wkl [ 256 * 1024 / 8];
__device__ uint4 g_wvh [ 256 * 1024 / 8], g_wvl [ 256 * 1024 / 8];
__device__ uint4 g_woh [1024 * 1024 / 8], g_wol [1024 * 1024 / 8];
__device__ uint4 g_Kh[8192 * 256 / 8], g_Kl[8192 * 256 / 8];
__device__ uint4 g_Vh[8192 * 256 / 8], g_Vl[8192 * 256 / 8];
__device__ uint4 g_AOh[1024 * 512 / 4], g_AOl[1024 * 512 / 4];

// ---------------- helpers ----------------
__device__ __forceinline__ uint32_t pack_bf(float x, float y) {
    uint32_t r;
    asm("cvt.rn.bf16x2.f32 %0, %1, %2;" : "=r"(r) : "f"(y), "f"(x));
    return r;
}
__device__ __forceinline__ void bfsplit2(float x, float y, uint32_t& h, uint32_t& l) {
    h = pack_bf(x, y);
    float hx = __uint_as_float(h << 16);
    float hy = __uint_as_float(h & 0xffff0000u);
    l = pack_bf(x - hx, y - hy);
}
__device__ __forceinline__ void mma16(float* d, const uint32_t* a, const uint32_t* b) {
    asm volatile(
        "mma.sync.aligned.m16n8k16.row.col.f32.bf16.bf16.f32 "
        "{%0,%1,%2,%3},{%4,%5,%6,%7},{%8,%9},{%0,%1,%2,%3};"
        : "+f"(d[0]), "+f"(d[1]), "+f"(d[2]), "+f"(d[3])
        : "r"(a[0]), "r"(a[1]), "r"(a[2]), "r"(a[3]), "r"(b[0]), "r"(b[1]));
}
__device__ __forceinline__ uint32_t smem_u32(const void* p) {
    uint32_t a;
    asm("{ .reg .u64 t; cvta.to.shared.u64 t, %1; cvt.u32.u64 %0, t; }" : "=r"(a) : "l"(p));
    return a;
}
__device__ __forceinline__ void ldsm4(uint32_t* r, uint32_t addr) {
    asm volatile("ldmatrix.sync.aligned.m8n8.x4.shared.b16 {%0,%1,%2,%3}, [%4];"
        : "=r"(r[0]), "=r"(r[1]), "=r"(r[2]), "=r"(r[3]) : "r"(addr));
}
__device__ __forceinline__ void ldsm4t(uint32_t* r, uint32_t addr) {
    asm volatile("ldmatrix.sync.aligned.m8n8.x4.trans.shared.b16 {%0,%1,%2,%3}, [%4];"
        : "=r"(r[0]), "=r"(r[1]), "=r"(r[2]), "=r"(r[3]) : "r"(addr));
}

// ======================================================================
// presplit: X (f32) -> Xh, Xl (bf16 halfs, same layout)
// ======================================================================
__global__ void presplit(const float4* __restrict__ x,
                         uint4* __restrict__ h, uint4* __restrict__ l, int n8)
{
    int i = blockIdx.x * blockDim.x + threadIdx.x;
    if (i >= n8) return;
    float4 v0 = x[2 * i], v1 = x[2 * i + 1];
    uint4 H, L;
    bfsplit2(v0.x, v0.y, H.x, L.x);
    bfsplit2(v0.z, v0.w, H.y, L.y);
    bfsplit2(v1.x, v1.y, H.z, L.z);
    bfsplit2(v1.z, v1.w, H.w, L.w);
    h[i] = H; l[i] = L;
}

// ======================================================================
// qkv_proj: fused Q/K/V projection. 640 blocks:
//   [0,256)  K = rmsnorm(inputs @ wk^T) -> bf16 hi/lo   (N=256)
//   [256,512) V = inputs @ wv^T        -> bf16 hi/lo    (N=256)
//   [512,640) Q = rmsnorm(latent @ wq^T) -> f32         (N=1024)
// Body identical to proven gemm_bf3 (LDG-register double-buffer + ldsm).
// ======================================================================
__global__ void __launch_bounds__(256, 2) qkv_proj(
    const uint16_t* __restrict__ lath, const uint16_t* __restrict__ latl,
    const uint16_t* __restrict__ inh,  const uint16_t* __restrict__ inl,
    const uint16_t* __restrict__ wqh,  const uint16_t* __restrict__ wql,
    const uint16_t* __restrict__ wkh,  const uint16_t* __restrict__ wkl,
    const uint16_t* __restrict__ wvh,  const uint16_t* __restrict__ wvl,
    const float* __restrict__ qnw, const float* __restrict__ knw,
    float* __restrict__ Qout,
    uint32_t* __restrict__ Kh, uint32_t* __restrict__ Kl,
    uint32_t* __restrict__ Vh, uint32_t* __restrict__ Vl)
{
    extern __shared__ char smc[];
    const uint32_t sb = smem_u32(smc);
    constexpr int STAGE = 30720;
    constexpr int O_AL = 10240, O_WH = 20480, O_WL = 25600;
    float* red = (float*)(smc + 2 * STAGE);

    // ---- per-block routing (block-uniform) ----
    const int bid = blockIdx.x;
    const uint16_t *Ah, *Al, *Wh, *Wl;
    const float* nw = nullptr;
    float* Cf = nullptr;
    uint32_t *Ch = nullptr, *Cl = nullptr;
    int m0, n0, N;
    bool norm, splitout;
    if (bid < 256) {            // K proj
        Ah = inh; Al = inl; Wh = wkh; Wl = wkl; nw = knw;
        norm = true; splitout = true; N = 256;
        n0 = (bid & 3) * 64; m0 = (bid >> 2) * 128;
        Ch = Kh; Cl = Kl;
    } else if (bid < 512) {     // V proj
        const int t = bid - 256;
        Ah = inh; Al = inl; Wh = wvh; Wl = wvl;
        norm = false; splitout = true; N = 256;
        n0 = (t & 3) * 64; m0 = (t >> 2) * 128;
        Ch = Vh; Cl = Vl;
    } else {                    // Q proj
        const int t = bid - 512;
        Ah = lath; Al = latl; Wh = wqh; Wl = wql; nw = qnw;
        norm = true; splitout = false; N = 1024;
        n0 = (t & 15) * 64; m0 = (t >> 4) * 128;
        Cf = Qout;
    }

    const int tid = threadIdx.x, lane = tid & 31, wid = tid >> 5;
    const int wm = wid >> 1, wn = wid & 1;
    const int g = lane >> 2, c = lane & 3;

    float acc[2][4][4];
#pragma unroll
    for (int mt = 0; mt < 2; mt++)
#pragma unroll
        for (int nt = 0; nt < 4; nt++)
#pragma unroll
            for (int i = 0; i < 4; i++) acc[mt][nt][i] = 0.f;

    const int srow = tid >> 2, sch = tid & 3;
    const size_t abase0 = (size_t)(m0 + srow) * HID + sch * 8;
    const size_t abase1 = (size_t)(m0 + srow + 64) * HID + sch * 8;
    const size_t wbase  = (size_t)(n0 + srow) * HID + sch * 8;
    const int ro = srow * 80 + sch * 16;

    uint4 rAh0, rAh1, rAl0, rAl1, rWh, rWl;
    auto LDGS = [&](int kt) {
        rAh0 = *(const uint4*)(Ah + abase0 + kt);
        rAh1 = *(const uint4*)(Ah + abase1 + kt);
        rAl0 = *(const uint4*)(Al + abase0 + kt);
        rAl1 = *(const uint4*)(Al + abase1 + kt);
        rWh  = *(const uint4*)(Wh + wbase + kt);
        rWl  = *(const uint4*)(Wl + wbase + kt);
    };
    auto STSS = [&](int buf) {
        char* d = smc + buf * STAGE;
        *(uint4*)(d + ro)                  = rAh0;
        *(uint4*)(d + 64 * 80 + ro)        = rAh1;
        *(uint4*)(d + O_AL + ro)           = rAl0;
        *(uint4*)(d + O_AL + 64 * 80 + ro) = rAl1;
        *(uint4*)(d + O_WH + ro)           = rWh;
        *(uint4*)(d + O_WL + ro)           = rWl;
    };

    const uint32_t aoff = (uint32_t)((wm * 32 + (lane & 7) + ((lane >> 3) & 1) * 8) * 80
                                     + ((lane >> 4) & 1) * 16);
    const uint32_t boff = (uint32_t)((wn * 32 + (lane & 7) + ((lane >> 4) & 1) * 8) * 80
                                     + ((lane >> 3) & 1) * 16);

    LDGS(0); STSS(0);
    __syncthreads();

    for (int kt = 0; kt < HID; kt += 32) {
        const int buf = (kt >> 5) & 1;
        const bool more = (kt + 32 < HID);
        if (more) LDGS(kt + 32);

        const uint32_t base = sb + buf * STAGE;
#pragma unroll
        for (int s = 0; s < 2; s++) {
            uint32_t ah[2][4], al[2][4], bhr[8], blr[8];
            ldsm4(bhr,     base + O_WH + boff + s * 32);
            ldsm4(bhr + 4, base + O_WH + boff + 16 * 80 + s * 32);
            ldsm4(blr,     base + O_WL + boff + s * 32);
            ldsm4(blr + 4, base + O_WL + boff + 16 * 80 + s * 32);
#pragma unroll
            for (int mt = 0; mt < 2; mt++) {
                ldsm4(ah[mt], base + aoff + mt * 1280 + s * 32);
                ldsm4(al[mt], base + O_AL + aoff + mt * 1280 + s * 32);
            }
#pragma unroll
            for (int mt = 0; mt < 2; mt++)
#pragma unroll
                for (int nt = 0; nt < 4; nt++) {
                    mma16(acc[mt][nt], ah[mt], bhr + 2 * nt);
                    mma16(acc[mt][nt], al[mt], bhr + 2 * nt);
                    mma16(acc[mt][nt], ah[mt], blr + 2 * nt);
                }
        }
        if (more) {
            __syncthreads();
            STSS(1 - buf);
            __syncthreads();
        }
    }

    if (norm) {
        __syncthreads();
        float ss0[2] = {0.f, 0.f}, ss1[2] = {0.f, 0.f};
#pragma unroll
        for (int mt = 0; mt < 2; mt++)
#pragma unroll
            for (int nt = 0; nt < 4; nt++) {
                ss0[mt] += acc[mt][nt][0] * acc[mt][nt][0] + acc[mt][nt][1] * acc[mt][nt][1];
                ss1[mt] += acc[mt][nt][2] * acc[mt][nt][2] + acc[mt][nt][3] * acc[mt][nt][3];
            }
#pragma unroll
        for (int mt = 0; mt < 2; mt++) {
            ss0[mt] += __shfl_xor_sync(0xffffffffu, ss0[mt], 1);
            ss0[mt] += __shfl_xor_sync(0xffffffffu, ss0[mt], 2);
            ss1[mt] += __shfl_xor_sync(0xffffffffu, ss1[mt], 1);
            ss1[mt] += __shfl_xor_sync(0xffffffffu, ss1[mt], 2);
            if (c == 0) {
                red[(wm * 32 + mt * 16 + g) * 2 + wn]     = ss0[mt];
                red[(wm * 32 + mt * 16 + g + 8) * 2 + wn] = ss1[mt];
            }
        }
        __syncthreads();
        float sc0[2], sc1[2];
#pragma unroll
        for (int mt = 0; mt < 2; mt++) {
            int r = (wm * 32 + mt * 16 + g) * 2;
            sc0[mt] = rsqrtf((red[r] + red[r + 1]) * (1.f / 64.f) + 1e-6f);
            r = (wm * 32 + mt * 16 + g + 8) * 2;
            sc1[mt] = rsqrtf((red[r] + red[r + 1]) * (1.f / 64.f) + 1e-6f);
        }
        float w0[4], w1[4];
#pragma unroll
        for (int nt = 0; nt < 4; nt++) {
            w0[nt] = nw[wn * 32 + nt * 8 + 2 * c];
            w1[nt] = nw[wn * 32 + nt * 8 + 2 * c + 1];
        }
#pragma unroll
        for (int mt = 0; mt < 2; mt++)
#pragma unroll
            for (int nt = 0; nt < 4; nt++) {
                acc[mt][nt][0] *= sc0[mt] * w0[nt];
                acc[mt][nt][1] *= sc0[mt] * w1[nt];
                acc[mt][nt][2] *= sc1[mt] * w0[nt];
                acc[mt][nt][3] *= sc1[mt] * w1[nt];
            }
    }

#pragma unroll
    for (int mt = 0; mt < 2; mt++)
#pragma unroll
        for (int nt = 0; nt < 4; nt++) {
            const int r = m0 + wm * 32 + mt * 16 + g;
            const int col = n0 + wn * 32 + nt * 8 + 2 * c;
            if (splitout) {
                uint32_t h0, l0, h1, l1;
                bfsplit2(acc[mt][nt][0], acc[mt][nt][1], h0, l0);
                bfsplit2(acc[mt][nt][2], acc[mt][nt][3], h1, l1);
                const int i0 = r * (N >> 1) + (col >> 1);
                const int i1 = (r + 8) * (N >> 1) + (col >> 1);
                Ch[i0] = h0; Cl[i0] = l0;
                Ch[i1] = h1; Cl[i1] = l1;
            } else {
                *(float2*)(Cf + (size_t)r * N + col) =
                    make_float2(acc[mt][nt][0], acc[mt][nt][1]);
                *(float2*)(Cf + (size_t)(r + 8) * N + col) =
                    make_float2(acc[mt][nt][2], acc[mt][nt][3]);
            }
        }
}

// ======================================================================
// gemm_bf3 (R12-proven): used for the O-projection only.
// ======================================================================
__global__ void __launch_bounds__(256, 2) gemm_bf3(
    const uint16_t* __restrict__ Ah, const uint16_t* __restrict__ Al,
    const uint16_t* __restrict__ Wh, const uint16_t* __restrict__ Wl,
    float* __restrict__ C, int M, int N, int Kdim)
{
    extern __shared__ char smc[];
    const uint32_t sb = smem_u32(smc);
    constexpr int STAGE = 30720;
    constexpr int O_AL = 10240, O_WH = 20480, O_WL = 25600;

    const int tid = threadIdx.x, lane = tid & 31, wid = tid >> 5;
    const int wm = wid >> 1, wn = wid & 1;
    const int g = lane >> 2, c = lane & 3;
    const int m0 = blockIdx.y * 128, n0 = blockIdx.x * 64;

    float acc[2][4][4];
#pragma unroll
    for (int mt = 0; mt < 2; mt++)
#pragma unroll
        for (int nt = 0; nt < 4; nt++)
#pragma unroll
            for (int i = 0; i < 4; i++) acc[mt][nt][i] = 0.f;

    const int srow = tid >> 2, sch = tid & 3;
    const size_t abase0 = (size_t)(m0 + srow) * Kdim + sch * 8;
    const size_t abase1 = (size_t)(m0 + srow + 64) * Kdim + sch * 8;
    const size_t wbase  = (size_t)(n0 + srow) * Kdim + sch * 8;
    const int ro = srow * 80 + sch * 16;

    uint4 rAh0, rAh1, rAl0, rAl1, rWh, rWl;
    auto LDGS = [&](int kt) {
        rAh0 = *(const uint4*)(Ah + abase0 + kt);
        rAh1 = *(const uint4*)(Ah + abase1 + kt);
        rAl0 = *(const uint4*)(Al + abase0 + kt);
        rAl1 = *(const uint4*)(Al + abase1 + kt);
        rWh  = *(const uint4*)(Wh + wbase + kt);
        rWl  = *(const uint4*)(Wl + wbase + kt);
    };
    auto STSS = [&](int buf) {
        char* d = smc + buf * STAGE;
        *(uint4*)(d + ro)                  = rAh0;
        *(uint4*)(d + 64 * 80 + ro)        = rAh1;
        *(uint4*)(d + O_AL + ro)           = rAl0;
        *(uint4*)(d + O_AL + 64 * 80 + ro) = rAl1;
        *(uint4*)(d + O_WH + ro)           = rWh;
        *(uint4*)(d + O_WL + ro)           = rWl;
    };

    const uint32_t aoff = (uint32_t)((wm * 32 + (lane & 7) + ((lane >> 3) & 1) * 8) * 80
                                     + ((lane >> 4) & 1) * 16);
    const uint32_t boff = (uint32_t)((wn * 32 + (lane & 7) + ((lane >> 4) & 1) * 8) * 80
                                     + ((lane >> 3) & 1) * 16);

    LDGS(0); STSS(0);
    __syncthreads();

    for (int kt = 0; kt < Kdim; kt += 32) {
        const int buf = (kt >> 5) & 1;
        const bool more = (kt + 32 < Kdim);
        if (more) LDGS(kt + 32);

        const uint32_t base = sb + buf * STAGE;
#pragma unroll
        for (int s = 0; s < 2; s++) {
            uint32_t ah[2][4], al[2][4], bhr[8], blr[8];
            ldsm4(bhr,     base + O_WH + boff + s * 32);
            ldsm4(bhr + 4, base + O_WH + boff + 16 * 80 + s * 32);
            ldsm4(blr,     base + O_WL + boff + s * 32);
            ldsm4(blr + 4, base + O_WL + boff + 16 * 80 + s * 32);
#pragma unroll
            for (int mt = 0; mt < 2; mt++) {
                ldsm4(ah[mt], base + aoff + mt * 1280 + s * 32);
                ldsm4(al[mt], base + O_AL + aoff + mt * 1280 + s * 32);
            }
#pragma unroll
            for (int mt = 0; mt < 2; mt++)
#pragma unroll
                for (int nt = 0; nt < 4; nt++) {
                    mma16(acc[mt][nt], ah[mt], bhr + 2 * nt);
                    mma16(acc[mt][nt], al[mt], bhr + 2 * nt);
                    mma16(acc[mt][nt], ah[mt], blr + 2 * nt);
                }
        }
        if (more) {
            __syncthreads();
            STSS(1 - buf);
            __syncthreads();
        }
    }

#pragma unroll
    for (int mt = 0; mt < 2; mt++)
#pragma unroll
        for (int nt = 0; nt < 4; nt++) {
            const int r = m0 + wm * 32 + mt * 16 + g;
            const int col = n0 + wn * 32 + nt * 8 + 2 * c;
            *(float2*)(C + (size_t)r * N + col) =
                make_float2(acc[mt][nt][0], acc[mt][nt][1]);
            *(float2*)(C + (size_t)(r + 8) * N + col) =
                make_float2(acc[mt][nt][2], acc[mt][nt][3]);
        }
}

// ======================================================================
// Attention (R12 body). Q pre-scaled by log2(e) -> p = exp2f(s).
// ======================================================================
__global__ void __launch_bounds__(256, 1) attn_mma(
    const float* __restrict__ Qg,
    const uint16_t* __restrict__ Khg, const uint16_t* __restrict__ Klg,
    const uint16_t* __restrict__ Vhg, const uint16_t* __restrict__ Vlg,
    uint32_t* __restrict__ AOh, uint32_t* __restrict__ AOl)
{
    extern __shared__ char smc[];
    constexpr int TILE_B = 9216;
    constexpr int BUF_B  = 4 * TILE_B;
    const uint32_t sbase = smem_u32(smc);

    const int tid = threadIdx.x;
    const int lane = tid & 31, w = tid >> 5;
    const int g = lane >> 2, c = lane & 3;
    const int r8 = lane & 7, mm = lane >> 3;
    const int b = blockIdx.z, hk = blockIdx.y, q0 = blockIdx.x * 32;
    const int head = hk * 4 + (w >> 1);
    const int qi = (w & 1) * 16;

    // ---- Q fragments: scale by log2(e), then double-bf16 hi/lo ----
    const float L2E = 1.4426950408889634f;
    uint32_t qh[4][4], ql[4][4];
    {
        const float* r0 = Qg + (size_t)(b * SQ + q0 + qi + g) * HID + head * DH;
        const float* r1 = r0 + 8 * (size_t)HID;
#pragma unroll
        for (int s = 0; s < 4; s++) {
            const int cs = 16 * s + 2 * c;
            bfsplit2(r0[cs] * L2E,     r0[cs + 1] * L2E, qh[s][0], ql[s][0]);
            bfsplit2(r1[cs] * L2E,     r1[cs + 1] * L2E, qh[s][1], ql[s][1]);
            bfsplit2(r0[cs + 8] * L2E, r0[cs + 9] * L2E, qh[s][2], ql[s][2]);
            bfsplit2(r1[cs + 8] * L2E, r1[cs + 9] * L2E, qh[s][3], ql[s][3]);
        }
    }

    const int crow = tid >> 2;
    const int cch2 = (tid & 3) * 2;
    uint4 rKH[2], rKL[2], rVH[2], rVL[2];
    auto LDGA = [&](int t) {
        const size_t srow = (size_t)(b * SKV + t * 64 + crow) * 256 + hk * 64;
#pragma unroll
        for (int u = 0; u < 2; u++) {
            const size_t soff = srow + (size_t)(cch2 + u) * 8;
            rKH[u] = *(const uint4*)(Khg + soff);
            rKL[u] = *(const uint4*)(Klg + soff);
            rVH[u] = *(const uint4*)(Vhg + soff);
            rVL[u] = *(const uint4*)(Vlg + soff);
        }
    };
    auto STSA = [&](int buf) {
        char* d = smc + buf * BUF_B;
#pragma unroll
        for (int u = 0; u < 2; u++) {
            const int doff = crow * 144 + (cch2 + u) * 16;
            *(uint4*)(d + doff)              = rKH[u];
            *(uint4*)(d + TILE_B + doff)     = rKL[u];
            *(uint4*)(d + 2 * TILE_B + doff) = rVH[u];
            *(uint4*)(d + 3 * TILE_B + doff) = rVL[u];
        }
    };

    float oacc[8][4];
#pragma unroll
    for (int j = 0; j < 8; j++)
#pragma unroll
        for (int i = 0; i < 4; i++) oacc[j][i] = 0.f;
    float lsum0 = 0.f, lsum1 = 0.f;

    const uint32_t k_off = (uint32_t)r8 * 144u + (uint32_t)mm * 16u;
    const uint32_t v_off = ((uint32_t)(8 * (mm & 1) + r8)) * 144u + (uint32_t)(mm >> 1) * 16u;

    LDGA(0); STSA(0);
    __syncthreads();

    for (int t = 0; t < SKV / 64; t++) {
        const int cur = t & 1;
        if (t < SKV / 64 - 1) LDGA(t + 1);

        const uint32_t kh_b = sbase + (uint32_t)cur * BUF_B;
        const uint32_t kl_b = kh_b + TILE_B;
        const uint32_t vh_b = kh_b + 2 * TILE_B;
        const uint32_t vl_b = kh_b + 3 * TILE_B;

        // --- S = Q @ K^T (3-term double-bf16), S already in log2 domain ---
        float sacc[8][4];
#pragma unroll
        for (int j = 0; j < 8; j++) {
            const uint32_t ro = (uint32_t)(8 * j) * 144u;
            uint32_t kh[8], kl[8];
            ldsm4(kh,     kh_b + ro + k_off);
            ldsm4(kh + 4, kh_b + ro + k_off + 64u);
            ldsm4(kl,     kl_b + ro + k_off);
            ldsm4(kl + 4, kl_b + ro + k_off + 64u);
#pragma unroll
            for (int i = 0; i < 4; i++) sacc[j][i] = 0.f;
#pragma unroll
            for (int s = 0; s < 4; s++) {
                mma16(sacc[j], qh[s], kh + 2 * s);
                mma16(sacc[j], ql[s], kh + 2 * s);
                mma16(sacc[j], qh[s], kl + 2 * s);
            }
        }

        // --- P = exp2(S): fp32 row-sum, bf16 hi/lo A-frags in regs ---
        uint32_t pah[4][4], pal[4][4];
        float rs0 = 0.f, rs1 = 0.f;
#pragma unroll
        for (int j = 0; j < 8; j++) {
            float p0 = exp2f(sacc[j][0]);
            float p1 = exp2f(sacc[j][1]);
            float p2 = exp2f(sacc[j][2]);
            float p3 = exp2f(sacc[j][3]);
            rs0 += p0 + p1;
            rs1 += p2 + p3;
            const int s = j >> 1, o = (j & 1) * 2;
            bfsplit2(p0, p1, pah[s][o],     pal[s][o]);
            bfsplit2(p2, p3, pah[s][o + 1], pal[s][o + 1]);
        }
        rs0 += __shfl_xor_sync(0xffffffffu, rs0, 1);
        rs0 += __shfl_xor_sync(0xffffffffu, rs0, 2);
        rs1 += __shfl_xor_sync(0xffffffffu, rs1, 1);
        rs1 += __shfl_xor_sync(0xffffffffu, rs1, 2);
        lsum0 += rs0;
        lsum1 += rs1;

        // --- O += P @ V (3-term double-bf16) ---
#pragma unroll
        for (int s = 0; s < 4; s++) {
            const uint32_t so = (uint32_t)(16 * s) * 144u;
#pragma unroll
            for (int jj = 0; jj < 4; jj++) {
                const uint32_t co = so + (uint32_t)(32 * jj) + v_off;
                uint32_t vh[4], vl[4];
                ldsm4t(vh, vh_b + co);
                ldsm4t(vl, vl_b + co);
                mma16(oacc[2 * jj],     pah[s], vh);
                mma16(oacc[2 * jj],     pal[s], vh);
                mma16(oacc[2 * jj],     pah[s], vl);
                mma16(oacc[2 * jj + 1], pah[s], vh + 2);
                mma16(oacc[2 * jj + 1], pal[s], vh + 2);
                mma16(oacc[2 * jj + 1], pah[s], vl + 2);
            }
        }

        if (t < SKV / 64 - 1) {
            __syncthreads();
            STSA(1 - cur);
            __syncthreads();
        }
    }

    // --- epilogue: normalize, write bf16 hi/lo split AO ---
    const float i0 = 1.f / lsum0, i1 = 1.f / lsum1;
    const int row0 = b * SQ + q0 + qi + g;
    const int colw = head * 32 + c;
#pragma unroll
    for (int j = 0; j < 8; j++) {
        uint32_t h0, l0, h1, l1;
        bfsplit2(oacc[j][0] * i0, oacc[j][1] * i0, h0, l0);
        bfsplit2(oacc[j][2] * i1, oacc[j][3] * i1, h1, l1);
        const int idx0 = row0 * 512 + colw + j * 4;
        const int idx1 = idx0 + 8 * 512;
        AOh[idx0] = h0; AOl[idx0] = l0;
        AOh[idx1] = h1; AOl[idx1] = l1;
    }
}

// ======================================================================
extern "C" void kernel_launch(void* const* d_in, const int* in_sizes, int n_in,
                              void* d_out, int out_size)
{
    (void)in_sizes; (void)n_in; (void)out_size;
    const float* inputs = (const float*)d_in[0];
    const float* latent = (const float*)d_in[1];
    const float* wq     = (const float*)d_in[2];
    const float* wk     = (const float*)d_in[3];
    const float* wv     = (const float*)d_in[4];
    const float* wo     = (const float*)d_in[5];
    const float* qnw    = (const float*)d_in[6];
    const float* knw    = (const float*)d_in[7];
    float* out = (float*)d_out;

    float* Qb;
    cudaGetSymbolAddress((void**)&Qb, g_Q);
    uint4 *inh, *inl, *lath, *latl, *wqh, *wql, *wkh, *wkl, *wvh, *wvl, *woh, *wol;
    cudaGetSymbolAddress((void**)&inh,  g_inh);  cudaGetSymbolAddress((void**)&inl,  g_inl);
    cudaGetSymbolAddress((void**)&lath, g_lath); cudaGetSymbolAddress((void**)&latl, g_latl);
    cudaGetSymbolAddress((void**)&wqh,  g_wqh);  cudaGetSymbolAddress((void**)&wql,  g_wql);
    cudaGetSymbolAddress((void**)&wkh,  g_wkh);  cudaGetSymbolAddress((void**)&wkl,  g_wkl);
    cudaGetSymbolAddress((void**)&wvh,  g_wvh);  cudaGetSymbolAddress((void**)&wvl,  g_wvl);
    cudaGetSymbolAddress((void**)&woh,  g_woh);  cudaGetSymbolAddress((void**)&wol,  g_wol);
    uint4 *kh4, *kl4, *vh4, *vl4, *aoh4, *aol4;
    cudaGetSymbolAddress((void**)&kh4, g_Kh);    cudaGetSymbolAddress((void**)&kl4, g_Kl);
    cudaGetSymbolAddress((void**)&vh4, g_Vh);    cudaGetSymbolAddress((void**)&vl4, g_Vl);
    cudaGetSymbolAddress((void**)&aoh4, g_AOh);  cudaGetSymbolAddress((void**)&aol4, g_AOl);

    const int SMG = 2 * 30720 + 1024;   // 62464
    const int SMA = 2 * 4 * 9216;       // 73728
    cudaFuncSetAttribute(qkv_proj, cudaFuncAttributeMaxDynamicSharedMemorySize, SMG);
    cudaFuncSetAttribute(gemm_bf3, cudaFuncAttributeMaxDynamicSharedMemorySize, SMG);
    cudaFuncSetAttribute(attn_mma, cudaFuncAttributeMaxDynamicSharedMemorySize, SMA);

    // ---- pre-split all GEMM operands to bf16 hi/lo ----
    auto split = [&](const float* x, uint4* h, uint4* l, int n) {
        int n8 = n / 8;
        presplit<<<(n8 + 255) / 256, 256>>>((const float4*)x, h, l, n8);
    };
    split(inputs, inh,  inl,  8192 * 1024);
    split(latent, lath, latl, 1024 * 1024);
    split(wq,     wqh,  wql,  1024 * 1024);
    split(wk,     wkh,  wkl,   256 * 1024);
    split(wv,     wvh,  wvl,   256 * 1024);
    split(wo,     woh,  wol,  1024 * 1024);

    dim3 blk(256);
    // fused Q/K/V projections (640 CTAs)
    qkv_proj<<<640, blk, SMG>>>(
        (const uint16_t*)lath, (const uint16_t*)latl,
        (const uint16_t*)inh,  (const uint16_t*)inl,
        (const uint16_t*)wqh,  (const uint16_t*)wql,
        (const uint16_t*)wkh,  (const uint16_t*)wkl,
        (const uint16_t*)wvh,  (const uint16_t*)wvl,
        qnw, knw, Qb,
        (uint32_t*)kh4, (uint32_t*)kl4, (uint32_t*)vh4, (uint32_t*)vl4);
    // attention -> bf16 hi/lo AO
    attn_mma<<<dim3(SQ / 32, NHK, BATCH), blk, SMA>>>(
        Qb, (const uint16_t*)kh4, (const uint16_t*)kl4,
        (const uint16_t*)vh4, (const uint16_t*)vl4,
        (uint32_t*)aoh4, (uint32_t*)aol4);
    // out = AO @ wo^T -> f32
    gemm_bf3<<<dim3(16, 8), blk, SMG>>>(
        (const uint16_t*)aoh4, (const uint16_t*)aol4,
        (const uint16_t*)woh, (const uint16_t*)wol,
        out, BATCH * SQ, HID, HID);
}

// round 14
// speedup vs baseline: 1.7502x; 1.0788x over previous
#include <cuda_runtime.h>
#include <cstdint>

#define HID   1024
#define BATCH 2
#define SKV   4096
#define SQ    512
#define NH    16
#define NHK   4
#define DH    64

// ---------------- scratch (all GEMM-consumed buffers uint4 => 16B aligned) ----------------
__device__ float g_Q [BATCH * SQ * NH * DH];
__device__ uint4 g_inh [8192 * 1024 / 8], g_inl [8192 * 1024 / 8];
__device__ uint4 g_lath[1024 * 1024 / 8], g_latl[1024 * 1024 / 8];
__device__ uint4 g_wqh [1024 * 1024 / 8], g_wql [1024 * 1024 / 8];
__device__ uint4 g_wkh [ 256 * 1024 / 8], g_wkl [ 256 * 1024 / 8];
__device__ uint4 g_wvh [ 256 * 1024 / 8], g_wvl [ 256 * 1024 / 8];
__device__ uint4 g_woh [1024 * 1024 / 8], g_wol [1024 * 1024 / 8];
__device__ uint4 g_Kh[8192 * 256 / 8], g_Kl[8192 * 256 / 8];
__device__ uint4 g_Vh[8192 * 256 / 8], g_Vl[8192 * 256 / 8];
__device__ uint4 g_AOh[1024 * 512 / 4], g_AOl[1024 * 512 / 4];

// ---------------- helpers ----------------
__device__ __forceinline__ uint32_t pack_bf(float x, float y) {
    uint32_t r;
    asm("cvt.rn.bf16x2.f32 %0, %1, %2;" : "=r"(r) : "f"(y), "f"(x));
    return r;
}
__device__ __forceinline__ void bfsplit2(float x, float y, uint32_t& h, uint32_t& l) {
    h = pack_bf(x, y);
    float hx = __uint_as_float(h << 16);
    float hy = __uint_as_float(h & 0xffff0000u);
    l = pack_bf(x - hx, y - hy);
}
__device__ __forceinline__ void mma16(float* d, const uint32_t* a, const uint32_t* b) {
    asm volatile(
        "mma.sync.aligned.m16n8k16.row.col.f32.bf16.bf16.f32 "
        "{%0,%1,%2,%3},{%4,%5,%6,%7},{%8,%9},{%0,%1,%2,%3};"
        : "+f"(d[0]), "+f"(d[1]), "+f"(d[2]), "+f"(d[3])
        : "r"(a[0]), "r"(a[1]), "r"(a[2]), "r"(a[3]), "r"(b[0]), "r"(b[1]));
}
__device__ __forceinline__ uint32_t smem_u32(const void* p) {
    uint32_t a;
    asm("{ .reg .u64 t; cvta.to.shared.u64 t, %1; cvt.u32.u64 %0, t; }" : "=r"(a) : "l"(p));
    return a;
}
__device__ __forceinline__ void ldsm4(uint32_t* r, uint32_t addr) {
    asm volatile("ldmatrix.sync.aligned.m8n8.x4.shared.b16 {%0,%1,%2,%3}, [%4];"
        : "=r"(r[0]), "=r"(r[1]), "=r"(r[2]), "=r"(r[3]) : "r"(addr));
}
__device__ __forceinline__ void ldsm4t(uint32_t* r, uint32_t addr) {
    asm volatile("ldmatrix.sync.aligned.m8n8.x4.trans.shared.b16 {%0,%1,%2,%3}, [%4];"
        : "=r"(r[0]), "=r"(r[1]), "=r"(r[2]), "=r"(r[3]) : "r"(addr));
}

// ======================================================================
// presplit_all: all six operand tensors in ONE launch.
// Segments (in units of 8 f32): inputs 1048576 | latent 131072 |
// wq 131072 | wk 32768 | wv 32768 | wo 131072 ; total 1507328 = 5888*256.
// ======================================================================
__global__ void __launch_bounds__(256) presplit_all(
    const float4* __restrict__ inp, const float4* __restrict__ lat,
    const float4* __restrict__ wq_, const float4* __restrict__ wk_,
    const float4* __restrict__ wv_, const float4* __restrict__ wo_,
    uint4* __restrict__ inh,  uint4* __restrict__ inl,
    uint4* __restrict__ lath, uint4* __restrict__ latl,
    uint4* __restrict__ wqh,  uint4* __restrict__ wql,
    uint4* __restrict__ wkh,  uint4* __restrict__ wkl,
    uint4* __restrict__ wvh,  uint4* __restrict__ wvl,
    uint4* __restrict__ woh,  uint4* __restrict__ wol)
{
    int i = blockIdx.x * blockDim.x + threadIdx.x;
    const float4* src;
    uint4 *h, *l;
    int o = i;
    if (o < 1048576)            { src = inp; h = inh;  l = inl;  }
    else if ((o -= 1048576) < 131072) { src = lat; h = lath; l = latl; }
    else if ((o -=  131072) < 131072) { src = wq_; h = wqh;  l = wql;  }
    else if ((o -=  131072) <  32768) { src = wk_; h = wkh;  l = wkl;  }
    else if ((o -=   32768) <  32768) { src = wv_; h = wvh;  l = wvl;  }
    else      { o -= 32768;       src = wo_; h = woh;  l = wol;  }

    float4 v0 = src[2 * o], v1 = src[2 * o + 1];
    uint4 H, L;
    bfsplit2(v0.x, v0.y, H.x, L.x);
    bfsplit2(v0.z, v0.w, H.y, L.y);
    bfsplit2(v1.x, v1.y, H.z, L.z);
    bfsplit2(v1.z, v1.w, H.w, L.w);
    h[o] = H; l[o] = L;
}

// ======================================================================
// qkv_proj: fused Q/K/V projection. 640 blocks:
//   [0,256)   K = rmsnorm(inputs @ wk^T) -> bf16 hi/lo   (N=256)
//   [256,512) V = inputs @ wv^T          -> bf16 hi/lo   (N=256)
//   [512,640) Q = rmsnorm(latent @ wq^T) * log2(e) -> f32 (N=1024)
// One barrier per K-chunk (pre-STS barrier is provably redundant).
// ======================================================================
__global__ void __launch_bounds__(256, 2) qkv_proj(
    const uint16_t* __restrict__ lath, const uint16_t* __restrict__ latl,
    const uint16_t* __restrict__ inh,  const uint16_t* __restrict__ inl,
    const uint16_t* __restrict__ wqh,  const uint16_t* __restrict__ wql,
    const uint16_t* __restrict__ wkh,  const uint16_t* __restrict__ wkl,
    const uint16_t* __restrict__ wvh,  const uint16_t* __restrict__ wvl,
    const float* __restrict__ qnw, const float* __restrict__ knw,
    float* __restrict__ Qout,
    uint32_t* __restrict__ Kh, uint32_t* __restrict__ Kl,
    uint32_t* __restrict__ Vh, uint32_t* __restrict__ Vl)
{
    extern __shared__ char smc[];
    const uint32_t sb = smem_u32(smc);
    constexpr int STAGE = 30720;
    constexpr int O_AL = 10240, O_WH = 20480, O_WL = 25600;
    float* red = (float*)(smc + 2 * STAGE);

    const int bid = blockIdx.x;
    const uint16_t *Ah, *Al, *Wh, *Wl;
    const float* nw = nullptr;
    float* Cf = nullptr;
    uint32_t *Ch = nullptr, *Cl = nullptr;
    int m0, n0, N;
    bool norm, splitout;
    float oscale = 1.0f;
    if (bid < 256) {            // K proj
        Ah = inh; Al = inl; Wh = wkh; Wl = wkl; nw = knw;
        norm = true; splitout = true; N = 256;
        n0 = (bid & 3) * 64; m0 = (bid >> 2) * 128;
        Ch = Kh; Cl = Kl;
    } else if (bid < 512) {     // V proj
        const int t = bid - 256;
        Ah = inh; Al = inl; Wh = wvh; Wl = wvl;
        norm = false; splitout = true; N = 256;
        n0 = (t & 3) * 64; m0 = (t >> 2) * 128;
        Ch = Vh; Cl = Vl;
    } else {                    // Q proj (pre-scaled by log2 e)
        const int t = bid - 512;
        Ah = lath; Al = latl; Wh = wqh; Wl = wql; nw = qnw;
        norm = true; splitout = false; N = 1024;
        n0 = (t & 15) * 64; m0 = (t >> 4) * 128;
        Cf = Qout;
        oscale = 1.4426950408889634f;
    }

    const int tid = threadIdx.x, lane = tid & 31, wid = tid >> 5;
    const int wm = wid >> 1, wn = wid & 1;
    const int g = lane >> 2, c = lane & 3;

    float acc[2][4][4];
#pragma unroll
    for (int mt = 0; mt < 2; mt++)
#pragma unroll
        for (int nt = 0; nt < 4; nt++)
#pragma unroll
            for (int i = 0; i < 4; i++) acc[mt][nt][i] = 0.f;

    const int srow = tid >> 2, sch = tid & 3;
    const size_t abase0 = (size_t)(m0 + srow) * HID + sch * 8;
    const size_t abase1 = (size_t)(m0 + srow + 64) * HID + sch * 8;
    const size_t wbase  = (size_t)(n0 + srow) * HID + sch * 8;
    const int ro = srow * 80 + sch * 16;

    uint4 rAh0, rAh1, rAl0, rAl1, rWh, rWl;
    auto LDGS = [&](int kt) {
        rAh0 = *(const uint4*)(Ah + abase0 + kt);
        rAh1 = *(const uint4*)(Ah + abase1 + kt);
        rAl0 = *(const uint4*)(Al + abase0 + kt);
        rAl1 = *(const uint4*)(Al + abase1 + kt);
        rWh  = *(const uint4*)(Wh + wbase + kt);
        rWl  = *(const uint4*)(Wl + wbase + kt);
    };
    auto STSS = [&](int buf) {
        char* d = smc + buf * STAGE;
        *(uint4*)(d + ro)                  = rAh0;
        *(uint4*)(d + 64 * 80 + ro)        = rAh1;
        *(uint4*)(d + O_AL + ro)           = rAl0;
        *(uint4*)(d + O_AL + 64 * 80 + ro) = rAl1;
        *(uint4*)(d + O_WH + ro)           = rWh;
        *(uint4*)(d + O_WL + ro)           = rWl;
    };

    const uint32_t aoff = (uint32_t)((wm * 32 + (lane & 7) + ((lane >> 3) & 1) * 8) * 80
                                     + ((lane >> 4) & 1) * 16);
    const uint32_t boff = (uint32_t)((wn * 32 + (lane & 7) + ((lane >> 4) & 1) * 8) * 80
                                     + ((lane >> 3) & 1) * 16);

    LDGS(0); STSS(0);
    __syncthreads();

    for (int kt = 0; kt < HID; kt += 32) {
        const int buf = (kt >> 5) & 1;
        const bool more = (kt + 32 < HID);
        if (more) LDGS(kt + 32);

        const uint32_t base = sb + buf * STAGE;
#pragma unroll
        for (int s = 0; s < 2; s++) {
            uint32_t ah[2][4], al[2][4], bhr[8], blr[8];
            ldsm4(bhr,     base + O_WH + boff + s * 32);
            ldsm4(bhr + 4, base + O_WH + boff + 16 * 80 + s * 32);
            ldsm4(blr,     base + O_WL + boff + s * 32);
            ldsm4(blr + 4, base + O_WL + boff + 16 * 80 + s * 32);
#pragma unroll
            for (int mt = 0; mt < 2; mt++) {
                ldsm4(ah[mt], base + aoff + mt * 1280 + s * 32);
                ldsm4(al[mt], base + O_AL + aoff + mt * 1280 + s * 32);
            }
#pragma unroll
            for (int mt = 0; mt < 2; mt++)
#pragma unroll
                for (int nt = 0; nt < 4; nt++) {
                    mma16(acc[mt][nt], ah[mt], bhr + 2 * nt);
                    mma16(acc[mt][nt], al[mt], bhr + 2 * nt);
                    mma16(acc[mt][nt], ah[mt], blr + 2 * nt);
                }
        }
        if (more) {
            STSS(1 - buf);     // safe: last reads of this buffer ended before
            __syncthreads();   // the previous chunk's barrier
        }
    }

    if (norm) {
        __syncthreads();
        float ss0[2] = {0.f, 0.f}, ss1[2] = {0.f, 0.f};
#pragma unroll
        for (int mt = 0; mt < 2; mt++)
#pragma unroll
            for (int nt = 0; nt < 4; nt++) {
                ss0[mt] += acc[mt][nt][0] * acc[mt][nt][0] + acc[mt][nt][1] * acc[mt][nt][1];
                ss1[mt] += acc[mt][nt][2] * acc[mt][nt][2] + acc[mt][nt][3] * acc[mt][nt][3];
            }
#pragma unroll
        for (int mt = 0; mt < 2; mt++) {
            ss0[mt] += __shfl_xor_sync(0xffffffffu, ss0[mt], 1);
            ss0[mt] += __shfl_xor_sync(0xffffffffu, ss0[mt], 2);
            ss1[mt] += __shfl_xor_sync(0xffffffffu, ss1[mt], 1);
            ss1[mt] += __shfl_xor_sync(0xffffffffu, ss1[mt], 2);
            if (c == 0) {
                red[(wm * 32 + mt * 16 + g) * 2 + wn]     = ss0[mt];
                red[(wm * 32 + mt * 16 + g + 8) * 2 + wn] = ss1[mt];
            }
        }
        __syncthreads();
        float sc0[2], sc1[2];
#pragma unroll
        for (int mt = 0; mt < 2; mt++) {
            int r = (wm * 32 + mt * 16 + g) * 2;
            sc0[mt] = rsqrtf((red[r] + red[r + 1]) * (1.f / 64.f) + 1e-6f);
            r = (wm * 32 + mt * 16 + g + 8) * 2;
            sc1[mt] = rsqrtf((red[r] + red[r + 1]) * (1.f / 64.f) + 1e-6f);
        }
        float w0[4], w1[4];
#pragma unroll
        for (int nt = 0; nt < 4; nt++) {
            w0[nt] = nw[wn * 32 + nt * 8 + 2 * c];
            w1[nt] = nw[wn * 32 + nt * 8 + 2 * c + 1];
        }
#pragma unroll
        for (int mt = 0; mt < 2; mt++)
#pragma unroll
            for (int nt = 0; nt < 4; nt++) {
                acc[mt][nt][0] *= sc0[mt] * w0[nt];
                acc[mt][nt][1] *= sc0[mt] * w1[nt];
                acc[mt][nt][2] *= sc1[mt] * w0[nt];
                acc[mt][nt][3] *= sc1[mt] * w1[nt];
            }
    }

#pragma unroll
    for (int mt = 0; mt < 2; mt++)
#pragma unroll
        for (int nt = 0; nt < 4; nt++) {
            const int r = m0 + wm * 32 + mt * 16 + g;
            const int col = n0 + wn * 32 + nt * 8 + 2 * c;
            if (splitout) {
                uint32_t h0, l0, h1, l1;
                bfsplit2(acc[mt][nt][0], acc[mt][nt][1], h0, l0);
                bfsplit2(acc[mt][nt][2], acc[mt][nt][3], h1, l1);
                const int i0 = r * (N >> 1) + (col >> 1);
                const int i1 = (r + 8) * (N >> 1) + (col >> 1);
                Ch[i0] = h0; Cl[i0] = l0;
                Ch[i1] = h1; Cl[i1] = l1;
            } else {
                *(float2*)(Cf + (size_t)r * N + col) =
                    make_float2(acc[mt][nt][0] * oscale, acc[mt][nt][1] * oscale);
                *(float2*)(Cf + (size_t)(r + 8) * N + col) =
                    make_float2(acc[mt][nt][2] * oscale, acc[mt][nt][3] * oscale);
            }
        }
}

// ======================================================================
// gemm_bf3: O-projection (R12-proven body, single barrier per chunk).
// ======================================================================
__global__ void __launch_bounds__(256, 2) gemm_bf3(
    const uint16_t* __restrict__ Ah, const uint16_t* __restrict__ Al,
    const uint16_t* __restrict__ Wh, const uint16_t* __restrict__ Wl,
    float* __restrict__ C, int M, int N, int Kdim)
{
    extern __shared__ char smc[];
    const uint32_t sb = smem_u32(smc);
    constexpr int STAGE = 30720;
    constexpr int O_AL = 10240, O_WH = 20480, O_WL = 25600;

    const int tid = threadIdx.x, lane = tid & 31, wid = tid >> 5;
    const int wm = wid >> 1, wn = wid & 1;
    const int g = lane >> 2, c = lane & 3;
    const int m0 = blockIdx.y * 128, n0 = blockIdx.x * 64;

    float acc[2][4][4];
#pragma unroll
    for (int mt = 0; mt < 2; mt++)
#pragma unroll
        for (int nt = 0; nt < 4; nt++)
#pragma unroll
            for (int i = 0; i < 4; i++) acc[mt][nt][i] = 0.f;

    const int srow = tid >> 2, sch = tid & 3;
    const size_t abase0 = (size_t)(m0 + srow) * Kdim + sch * 8;
    const size_t abase1 = (size_t)(m0 + srow + 64) * Kdim + sch * 8;
    const size_t wbase  = (size_t)(n0 + srow) * Kdim + sch * 8;
    const int ro = srow * 80 + sch * 16;

    uint4 rAh0, rAh1, rAl0, rAl1, rWh, rWl;
    auto LDGS = [&](int kt) {
        rAh0 = *(const uint4*)(Ah + abase0 + kt);
        rAh1 = *(const uint4*)(Ah + abase1 + kt);
        rAl0 = *(const uint4*)(Al + abase0 + kt);
        rAl1 = *(const uint4*)(Al + abase1 + kt);
        rWh  = *(const uint4*)(Wh + wbase + kt);
        rWl  = *(const uint4*)(Wl + wbase + kt);
    };
    auto STSS = [&](int buf) {
        char* d = smc + buf * STAGE;
        *(uint4*)(d + ro)                  = rAh0;
        *(uint4*)(d + 64 * 80 + ro)        = rAh1;
        *(uint4*)(d + O_AL + ro)           = rAl0;
        *(uint4*)(d + O_AL + 64 * 80 + ro) = rAl1;
        *(uint4*)(d + O_WH + ro)           = rWh;
        *(uint4*)(d + O_WL + ro)           = rWl;
    };

    const uint32_t aoff = (uint32_t)((wm * 32 + (lane & 7) + ((lane >> 3) & 1) * 8) * 80
                                     + ((lane >> 4) & 1) * 16);
    const uint32_t boff = (uint32_t)((wn * 32 + (lane & 7) + ((lane >> 4) & 1) * 8) * 80
                                     + ((lane >> 3) & 1) * 16);

    LDGS(0); STSS(0);
    __syncthreads();

    for (int kt = 0; kt < Kdim; kt += 32) {
        const int buf = (kt >> 5) & 1;
        const bool more = (kt + 32 < Kdim);
        if (more) LDGS(kt + 32);

        const uint32_t base = sb + buf * STAGE;
#pragma unroll
        for (int s = 0; s < 2; s++) {
            uint32_t ah[2][4], al[2][4], bhr[8], blr[8];
            ldsm4(bhr,     base + O_WH + boff + s * 32);
            ldsm4(bhr + 4, base + O_WH + boff + 16 * 80 + s * 32);
            ldsm4(blr,     base + O_WL + boff + s * 32);
            ldsm4(blr + 4, base + O_WL + boff + 16 * 80 + s * 32);
#pragma unroll
            for (int mt = 0; mt < 2; mt++) {
                ldsm4(ah[mt], base + aoff + mt * 1280 + s * 32);
                ldsm4(al[mt], base + O_AL + aoff + mt * 1280 + s * 32);
            }
#pragma unroll
            for (int mt = 0; mt < 2; mt++)
#pragma unroll
                for (int nt = 0; nt < 4; nt++) {
                    mma16(acc[mt][nt], ah[mt], bhr + 2 * nt);
                    mma16(acc[mt][nt], al[mt], bhr + 2 * nt);
                    mma16(acc[mt][nt], ah[mt], blr + 2 * nt);
                }
        }
        if (more) {
            STSS(1 - buf);
            __syncthreads();
        }
    }

#pragma unroll
    for (int mt = 0; mt < 2; mt++)
#pragma unroll
        for (int nt = 0; nt < 4; nt++) {
            const int r = m0 + wm * 32 + mt * 16 + g;
            const int col = n0 + wn * 32 + nt * 8 + 2 * c;
            *(float2*)(C + (size_t)r * N + col) =
                make_float2(acc[mt][nt][0], acc[mt][nt][1]);
            *(float2*)(C + (size_t)(r + 8) * N + col) =
                make_float2(acc[mt][nt][2], acc[mt][nt][3]);
        }
}

// ======================================================================
// Attention (R13 body, Q already log2e-scaled, single barrier per tile).
// ======================================================================
__global__ void __launch_bounds__(256, 1) attn_mma(
    const float* __restrict__ Qg,
    const uint16_t* __restrict__ Khg, const uint16_t* __restrict__ Klg,
    const uint16_t* __restrict__ Vhg, const uint16_t* __restrict__ Vlg,
    uint32_t* __restrict__ AOh, uint32_t* __restrict__ AOl)
{
    extern __shared__ char smc[];
    constexpr int TILE_B = 9216;
    constexpr int BUF_B  = 4 * TILE_B;
    const uint32_t sbase = smem_u32(smc);

    const int tid = threadIdx.x;
    const int lane = tid & 31, w = tid >> 5;
    const int g = lane >> 2, c = lane & 3;
    const int r8 = lane & 7, mm = lane >> 3;
    const int b = blockIdx.z, hk = blockIdx.y, q0 = blockIdx.x * 32;
    const int head = hk * 4 + (w >> 1);
    const int qi = (w & 1) * 16;

    // ---- Q fragments (already scaled by log2 e): double-bf16 hi/lo ----
    uint32_t qh[4][4], ql[4][4];
    {
        const float* r0 = Qg + (size_t)(b * SQ + q0 + qi + g) * HID + head * DH;
        const float* r1 = r0 + 8 * (size_t)HID;
#pragma unroll
        for (int s = 0; s < 4; s++) {
            const int cs = 16 * s + 2 * c;
            bfsplit2(r0[cs],     r0[cs + 1], qh[s][0], ql[s][0]);
            bfsplit2(r1[cs],     r1[cs + 1], qh[s][1], ql[s][1]);
            bfsplit2(r0[cs + 8], r0[cs + 9], qh[s][2], ql[s][2]);
            bfsplit2(r1[cs + 8], r1[cs + 9], qh[s][3], ql[s][3]);
        }
    }

    const int crow = tid >> 2;
    const int cch2 = (tid & 3) * 2;
    uint4 rKH[2], rKL[2], rVH[2], rVL[2];
    auto LDGA = [&](int t) {
        const size_t srow = (size_t)(b * SKV + t * 64 + crow) * 256 + hk * 64;
#pragma unroll
        for (int u = 0; u < 2; u++) {
            const size_t soff = srow + (size_t)(cch2 + u) * 8;
            rKH[u] = *(const uint4*)(Khg + soff);
            rKL[u] = *(const uint4*)(Klg + soff);
            rVH[u] = *(const uint4*)(Vhg + soff);
            rVL[u] = *(const uint4*)(Vlg + soff);
        }
    };
    auto STSA = [&](int buf) {
        char* d = smc + buf * BUF_B;
#pragma unroll
        for (int u = 0; u < 2; u++) {
            const int doff = crow * 144 + (cch2 + u) * 16;
            *(uint4*)(d + doff)              = rKH[u];
            *(uint4*)(d + TILE_B + doff)     = rKL[u];
            *(uint4*)(d + 2 * TILE_B + doff) = rVH[u];
            *(uint4*)(d + 3 * TILE_B + doff) = rVL[u];
        }
    };

    float oacc[8][4];
#pragma unroll
    for (int j = 0; j < 8; j++)
#pragma unroll
        for (int i = 0; i < 4; i++) oacc[j][i] = 0.f;
    float lsum0 = 0.f, lsum1 = 0.f;

    const uint32_t k_off = (uint32_t)r8 * 144u + (uint32_t)mm * 16u;
    const uint32_t v_off = ((uint32_t)(8 * (mm & 1) + r8)) * 144u + (uint32_t)(mm >> 1) * 16u;

    LDGA(0); STSA(0);
    __syncthreads();

    for (int t = 0; t < SKV / 64; t++) {
        const int cur = t & 1;
        if (t < SKV / 64 - 1) LDGA(t + 1);

        const uint32_t kh_b = sbase + (uint32_t)cur * BUF_B;
        const uint32_t kl_b = kh_b + TILE_B;
        const uint32_t vh_b = kh_b + 2 * TILE_B;
        const uint32_t vl_b = kh_b + 3 * TILE_B;

        // --- S = Q @ K^T (3-term double-bf16), log2 domain ---
        float sacc[8][4];
#pragma unroll
        for (int j = 0; j < 8; j++) {
            const uint32_t ro = (uint32_t)(8 * j) * 144u;
            uint32_t kh[8], kl[8];
            ldsm4(kh,     kh_b + ro + k_off);
            ldsm4(kh + 4, kh_b + ro + k_off + 64u);
            ldsm4(kl,     kl_b + ro + k_off);
            ldsm4(kl + 4, kl_b + ro + k_off + 64u);
#pragma unroll
            for (int i = 0; i < 4; i++) sacc[j][i] = 0.f;
#pragma unroll
            for (int s = 0; s < 4; s++) {
                mma16(sacc[j], qh[s], kh + 2 * s);
                mma16(sacc[j], ql[s], kh + 2 * s);
                mma16(sacc[j], qh[s], kl + 2 * s);
            }
        }

        // --- P = exp2(S): fp32 row-sum, bf16 hi/lo A-frags in regs ---
        uint32_t pah[4][4], pal[4][4];
        float rs0 = 0.f, rs1 = 0.f;
#pragma unroll
        for (int j = 0; j < 8; j++) {
            float p0 = exp2f(sacc[j][0]);
            float p1 = exp2f(sacc[j][1]);
            float p2 = exp2f(sacc[j][2]);
            float p3 = exp2f(sacc[j][3]);
            rs0 += p0 + p1;
            rs1 += p2 + p3;
            const int s = j >> 1, o = (j & 1) * 2;
            bfsplit2(p0, p1, pah[s][o],     pal[s][o]);
            bfsplit2(p2, p3, pah[s][o + 1], pal[s][o + 1]);
        }
        rs0 += __shfl_xor_sync(0xffffffffu, rs0, 1);
        rs0 += __shfl_xor_sync(0xffffffffu, rs0, 2);
        rs1 += __shfl_xor_sync(0xffffffffu, rs1, 1);
        rs1 += __shfl_xor_sync(0xffffffffu, rs1, 2);
        lsum0 += rs0;
        lsum1 += rs1;

        // --- O += P @ V (3-term double-bf16) ---
#pragma unroll
        for (int s = 0; s < 4; s++) {
            const uint32_t so = (uint32_t)(16 * s) * 144u;
#pragma unroll
            for (int jj = 0; jj < 4; jj++) {
                const uint32_t co = so + (uint32_t)(32 * jj) + v_off;
                uint32_t vh[4], vl[4];
                ldsm4t(vh, vh_b + co);
                ldsm4t(vl, vl_b + co);
                mma16(oacc[2 * jj],     pah[s], vh);
                mma16(oacc[2 * jj],     pal[s], vh);
                mma16(oacc[2 * jj],     pah[s], vl);
                mma16(oacc[2 * jj + 1], pah[s], vh + 2);
                mma16(oacc[2 * jj + 1], pal[s], vh + 2);
                mma16(oacc[2 * jj + 1], pah[s], vl + 2);
            }
        }

        if (t < SKV / 64 - 1) {
            STSA(1 - cur);     // safe: last reads of this buffer ended before
            __syncthreads();   // the previous tile's barrier
        }
    }

    // --- epilogue: normalize, write bf16 hi/lo split AO ---
    const float i0 = 1.f / lsum0, i1 = 1.f / lsum1;
    const int row0 = b * SQ + q0 + qi + g;
    const int colw = head * 32 + c;
#pragma unroll
    for (int j = 0; j < 8; j++) {
        uint32_t h0, l0, h1, l1;
        bfsplit2(oacc[j][0] * i0, oacc[j][1] * i0, h0, l0);
        bfsplit2(oacc[j][2] * i1, oacc[j][3] * i1, h1, l1);
        const int idx0 = row0 * 512 + colw + j * 4;
        const int idx1 = idx0 + 8 * 512;
        AOh[idx0] = h0; AOl[idx0] = l0;
        AOh[idx1] = h1; AOl[idx1] = l1;
    }
}

// ======================================================================
extern "C" void kernel_launch(void* const* d_in, const int* in_sizes, int n_in,
                              void* d_out, int out_size)
{
    (void)in_sizes; (void)n_in; (void)out_size;
    const float* inputs = (const float*)d_in[0];
    const float* latent = (const float*)d_in[1];
    const float* wq     = (const float*)d_in[2];
    const float* wk     = (const float*)d_in[3];
    const float* wv     = (const float*)d_in[4];
    const float* wo     = (const float*)d_in[5];
    const float* qnw    = (const float*)d_in[6];
    const float* knw    = (const float*)d_in[7];
    float* out = (float*)d_out;

    float* Qb;
    cudaGetSymbolAddress((void**)&Qb, g_Q);
    uint4 *inh, *inl, *lath, *latl, *wqh, *wql, *wkh, *wkl, *wvh, *wvl, *woh, *wol;
    cudaGetSymbolAddress((void**)&inh,  g_inh);  cudaGetSymbolAddress((void**)&inl,  g_inl);
    cudaGetSymbolAddress((void**)&lath, g_lath); cudaGetSymbolAddress((void**)&latl, g_latl);
    cudaGetSymbolAddress((void**)&wqh,  g_wqh);  cudaGetSymbolAddress((void**)&wql,  g_wql);
    cudaGetSymbolAddress((void**)&wkh,  g_wkh);  cudaGetSymbolAddress((void**)&wkl,  g_wkl);
    cudaGetSymbolAddress((void**)&wvh,  g_wvh);  cudaGetSymbolAddress((void**)&wvl,  g_wvl);
    cudaGetSymbolAddress((void**)&woh,  g_woh);  cudaGetSymbolAddress((void**)&wol,  g_wol);
    uint4 *kh4, *kl4, *vh4, *vl4, *aoh4, *aol4;
    cudaGetSymbolAddress((void**)&kh4, g_Kh);    cudaGetSymbolAddress((void**)&kl4, g_Kl);
    cudaGetSymbolAddress((void**)&vh4, g_Vh);    cudaGetSymbolAddress((void**)&vl4, g_Vl);
    cudaGetSymbolAddress((void**)&aoh4, g_AOh);  cudaGetSymbolAddress((void**)&aol4, g_AOl);

    const int SMG = 2 * 30720 + 1024;   // 62464
    const int SMA = 2 * 4 * 9216;       // 73728
    cudaFuncSetAttribute(qkv_proj, cudaFuncAttributeMaxDynamicSharedMemorySize, SMG);
    cudaFuncSetAttribute(gemm_bf3, cudaFuncAttributeMaxDynamicSharedMemorySize, SMG);
    cudaFuncSetAttribute(attn_mma, cudaFuncAttributeMaxDynamicSharedMemorySize, SMA);

    dim3 blk(256);
    // one fused presplit: 1507328 n8-items = 5888 * 256
    presplit_all<<<5888, blk>>>(
        (const float4*)inputs, (const float4*)latent, (const float4*)wq,
        (const float4*)wk, (const float4*)wv, (const float4*)wo,
        inh, inl, lath, latl, wqh, wql, wkh, wkl, wvh, wvl, woh, wol);
    // fused Q/K/V projections (640 CTAs)
    qkv_proj<<<640, blk, SMG>>>(
        (const uint16_t*)lath, (const uint16_t*)latl,
        (const uint16_t*)inh,  (const uint16_t*)inl,
        (const uint16_t*)wqh,  (const uint16_t*)wql,
        (const uint16_t*)wkh,  (const uint16_t*)wkl,
        (const uint16_t*)wvh,  (const uint16_t*)wvl,
        qnw, knw, Qb,
        (uint32_t*)kh4, (uint32_t*)kl4, (uint32_t*)vh4, (uint32_t*)vl4);
    // attention -> bf16 hi/lo AO
    attn_mma<<<dim3(SQ / 32, NHK, BATCH), blk, SMA>>>(
        Qb, (const uint16_t*)kh4, (const uint16_t*)kl4,
        (const uint16_t*)vh4, (const uint16_t*)vl4,
        (uint32_t*)aoh4, (uint32_t*)aol4);
    // out = AO @ wo^T -> f32
    gemm_bf3<<<dim3(16, 8), blk, SMG>>>(
        (const uint16_t*)aoh4, (const uint16_t*)aol4,
        (const uint16_t*)woh, (const uint16_t*)wol,
        out, BATCH * SQ, HID, HID);
}